// round 7
// baseline (speedup 1.0000x reference)
#include <cuda_runtime.h>
#include <cuda_bf16.h>
#include <math.h>
#include <stdint.h>

#define NN 50000
#define EE 800000
#define DH 256
#define NL 8
#define NTILES ((NN + 127) / 128)   // 391
#define NPAD (NTILES * 128)

// ---------------- scratch ----------------
__device__ float g_ha[NN * DH];   // h ping
__device__ float g_hb[NN * DH];   // h pong
__device__ __align__(16) __nv_bfloat16 g_xh[(size_t)NPAD * 256];      // x0 hi [node][k]
__device__ __align__(16) __nv_bfloat16 g_xl[(size_t)NPAD * 256];      // x0 lo
__device__ __align__(16) __nv_bfloat16 g_bhh[(size_t)NL * 512 * 256]; // B' hi [layer][k][n]
__device__ __align__(16) __nv_bfloat16 g_bll[(size_t)NL * 512 * 256]; // B' lo
__device__ float g_dis[NN];
__device__ int   g_counts[NN];
__device__ int   g_cursor[NN];
__device__ int   g_rowptr[NN + 1];
__device__ int   g_csr[EE];
__device__ float g_part[NTILES + 8];
__device__ float g_part2[NTILES + 8];

// ---------------- helpers ----------------
__device__ __forceinline__ uint32_t s2u(const void* p) {
    uint32_t a;
    asm("{ .reg .u64 t; cvta.to.shared.u64 t, %1; cvt.u32.u64 %0, t; }" : "=r"(a) : "l"(p));
    return a;
}
__device__ __forceinline__ void cp16(uint32_t dst, const void* src) {
    asm volatile("cp.async.cg.shared.global [%0], [%1], 16;" :: "r"(dst), "l"(src) : "memory");
}
#define CP_COMMIT() asm volatile("cp.async.commit_group;" ::: "memory")
#define CP_WAIT(n)  asm volatile("cp.async.wait_group %0;" :: "n"(n) : "memory")

#define LDSM4(r0,r1,r2,r3,a) \
    asm volatile("ldmatrix.sync.aligned.m8n8.x4.shared.b16 {%0,%1,%2,%3}, [%4];" \
                 : "=r"(r0),"=r"(r1),"=r"(r2),"=r"(r3) : "r"(a))
#define LDSM4T(r0,r1,r2,r3,a) \
    asm volatile("ldmatrix.sync.aligned.m8n8.x4.trans.shared.b16 {%0,%1,%2,%3}, [%4];" \
                 : "=r"(r0),"=r"(r1),"=r"(r2),"=r"(r3) : "r"(a))
#define MMA_BF16(c,a,b0,b1) \
    asm volatile("mma.sync.aligned.m16n8k16.row.col.f32.bf16.bf16.f32 " \
                 "{%0,%1,%2,%3}, {%4,%5,%6,%7}, {%8,%9}, {%0,%1,%2,%3};" \
                 : "+f"((c)[0]),"+f"((c)[1]),"+f"((c)[2]),"+f"((c)[3]) \
                 : "r"((a)[0]),"r"((a)[1]),"r"((a)[2]),"r"((a)[3]),"r"(b0),"r"(b1))

__device__ __forceinline__ void split_bf16(float v, __nv_bfloat16& h, __nv_bfloat16& l) {
    h = __float2bfloat16_rn(v);
    l = __float2bfloat16_rn(v - __bfloat162float(h));
}

// ---------------- graph preprocessing ----------------
__global__ void k_init(int n) {
    int i = blockIdx.x * blockDim.x + threadIdx.x;
    if (i < n) { g_counts[i] = 0; g_cursor[i] = 0; }
}
__global__ void k_count(const int* __restrict__ col, int E) {
    int e = blockIdx.x * blockDim.x + threadIdx.x;
    if (e < E) atomicAdd(&g_counts[col[e]], 1);
}
__global__ void k_scan(int n, int E) {
    __shared__ int sh[1024];
    int tid = threadIdx.x;
    int C = (n + 1023) >> 10;
    int base = tid * C;
    int s = 0;
    for (int i = 0; i < C; i++) { int idx = base + i; if (idx < n) s += g_counts[idx]; }
    sh[tid] = s; __syncthreads();
    for (int off = 1; off < 1024; off <<= 1) {
        int v = (tid >= off) ? sh[tid - off] : 0;
        __syncthreads();
        sh[tid] += v;
        __syncthreads();
    }
    int run = (tid > 0) ? sh[tid - 1] : 0;
    for (int i = 0; i < C; i++) {
        int idx = base + i;
        if (idx < n) {
            g_rowptr[idx] = run;
            int c = g_counts[idx];
            run += c;
            g_dis[idx] = rsqrtf((float)(c + 1));
        }
    }
    if (tid == 0) g_rowptr[n] = E;
}
__global__ void k_scatter(const int* __restrict__ row, const int* __restrict__ col, int E) {
    int e = blockIdx.x * blockDim.x + threadIdx.x;
    if (e < E) {
        int c = col[e];
        int p = g_rowptr[c] + atomicAdd(&g_cursor[c], 1);
        g_csr[p] = row[e];
    }
}

// ---------------- B' prep ----------------
__global__ void k_prep_b(const float* __restrict__ w1, const float* __restrict__ w2) {
    int idx = blockIdx.x * blockDim.x + threadIdx.x;
    if (idx >= NL * 512 * 256) return;
    int n = idx & 255;
    int k = (idx >> 8) & 511;
    int l = idx >> 17;
    float beta = logf(1.0f / (float)(l + 1) + 1.0f);
    float v = (k < 256) ? w1[(l << 16) + (k << 8) + n]
                        : w2[(l << 16) + ((k - 256) << 8) + n];
    float val = 0.5f * beta * v;
    if (k == n || k == n + 256) val += 0.5f * (1.0f - beta);
    __nv_bfloat16 h, lo; split_bf16(val, h, lo);
    g_bhh[idx] = h;
    g_bll[idx] = lo;
}

// ---------------- fused gather + 3-pass bf16 tensor GEMM + LN partials ----------------
// Layer l: reads h_in = (l even ? g_ha : g_hb), writes h_out = other buffer.
#define SMX 131072u
#define SMTOT 229376
__global__ __launch_bounds__(256, 1) void k_fused(int layer, int nvalid) {
    extern __shared__ char smem[];
    uint32_t sb = s2u(smem);
    const uint32_t Y = sb + SMX;
    const int tid = threadIdx.x, lane = tid & 31, wid = tid >> 5;
    const int T = blockIdx.x;

    const float* __restrict__ hin = (layer & 1) ? g_hb : g_ha;
    float* __restrict__ hout      = (layer & 1) ? g_ha : g_hb;

    const __nv_bfloat16* __restrict__ Bgh = g_bhh + (size_t)layer * 512 * 256;
    const __nv_bfloat16* __restrict__ Bgl = g_bll + (size_t)layer * 512 * 256;

    auto load_B = [&](int c, uint32_t bdst) {   // hi 32KB at bdst (2x16KB n-halves), lo at +32768
#pragma unroll
        for (int i = 0; i < 8; i++) {
            int e = tid + i * 256;
            int k = e >> 5, ncol = e & 31;
            int nhalf = ncol >> 4, nc = ncol & 15;
            uint32_t off = (uint32_t)(nhalf * 16384 + k * 256 + ((nc ^ (k & 7)) << 4));
            size_t src = (size_t)(c * 64 + k) * 256 + nhalf * 128 + nc * 8;
            cp16(bdst + off, Bgh + src);
            cp16(bdst + 32768 + off, Bgl + src);
        }
    };
    auto load_Ax0 = [&](int c, uint32_t adst) { // hi 16KB at adst, lo at +16384
#pragma unroll
        for (int i = 0; i < 4; i++) {
            int e = tid + i * 256;
            int m = e >> 3, kc = e & 7;
            uint32_t off = (uint32_t)(m * 128 + ((kc ^ (m & 7)) << 4));
            size_t src = (size_t)(T * 128 + m) * 256 + (c - 4) * 64 + kc * 8;
            cp16(adst + off, g_xh + src);
            cp16(adst + 16384 + off, g_xl + src);
        }
    };

    // prefetch B chunk 0 while gathering
    load_B(0, Y); CP_COMMIT();

    // ---- gather phase: 16 rows per warp into X (agg bf16 hi/lo, mma-swizzled) ----
    {
        const float4* __restrict__ h4 = (const float4*)hin;
        const int c0 = lane >> 4;
        const int kcu = (lane >> 1) & 7;
        const int sub = lane & 1;
        for (int rr = 0; rr < 16; rr++) {
            int m = wid * 16 + rr;
            int g = T * 128 + m;
            float4 a0 = make_float4(0.f, 0.f, 0.f, 0.f);
            float4 a1 = a0;
            if (g < nvalid) {
                float dc = g_dis[g];
                int base = g * 64;
                float4 v0 = h4[base + lane], v1 = h4[base + 32 + lane];
                a0.x = dc * v0.x; a0.y = dc * v0.y; a0.z = dc * v0.z; a0.w = dc * v0.w;
                a1.x = dc * v1.x; a1.y = dc * v1.y; a1.z = dc * v1.z; a1.w = dc * v1.w;
                int beg = g_rowptr[g], end = g_rowptr[g + 1];
                int i = beg;
                for (; i + 3 < end; i += 4) {
                    int s0 = g_csr[i], s1 = g_csr[i + 1], s2 = g_csr[i + 2], s3 = g_csr[i + 3];
                    float w0 = g_dis[s0], w1 = g_dis[s1], w2 = g_dis[s2], w3 = g_dis[s3];
                    float4 p0 = h4[s0 * 64 + lane], p1 = h4[s0 * 64 + 32 + lane];
                    float4 q0 = h4[s1 * 64 + lane], q1 = h4[s1 * 64 + 32 + lane];
                    float4 r0 = h4[s2 * 64 + lane], r1 = h4[s2 * 64 + 32 + lane];
                    float4 t0 = h4[s3 * 64 + lane], t1 = h4[s3 * 64 + 32 + lane];
                    a0.x += w0 * p0.x + w1 * q0.x + w2 * r0.x + w3 * t0.x;
                    a0.y += w0 * p0.y + w1 * q0.y + w2 * r0.y + w3 * t0.y;
                    a0.z += w0 * p0.z + w1 * q0.z + w2 * r0.z + w3 * t0.z;
                    a0.w += w0 * p0.w + w1 * q0.w + w2 * r0.w + w3 * t0.w;
                    a1.x += w0 * p1.x + w1 * q1.x + w2 * r1.x + w3 * t1.x;
                    a1.y += w0 * p1.y + w1 * q1.y + w2 * r1.y + w3 * t1.y;
                    a1.z += w0 * p1.z + w1 * q1.z + w2 * r1.z + w3 * t1.z;
                    a1.w += w0 * p1.w + w1 * q1.w + w2 * r1.w + w3 * t1.w;
                }
                for (; i < end; i++) {
                    int s0 = g_csr[i];
                    float w0 = g_dis[s0];
                    float4 p0 = h4[s0 * 64 + lane], p1 = h4[s0 * 64 + 32 + lane];
                    a0.x += w0 * p0.x; a0.y += w0 * p0.y; a0.z += w0 * p0.z; a0.w += w0 * p0.w;
                    a1.x += w0 * p1.x; a1.y += w0 * p1.y; a1.z += w0 * p1.z; a1.w += w0 * p1.w;
                }
                a0.x *= dc; a0.y *= dc; a0.z *= dc; a0.w *= dc;
                a1.x *= dc; a1.y *= dc; a1.z *= dc; a1.w *= dc;
            }
            uint32_t swz = (uint32_t)(m * 128 + ((kcu ^ (m & 7)) << 4) + sub * 8);
            char* p0 = smem + c0 * 32768 + swz;
            char* p1 = smem + (2 + c0) * 32768 + swz;
            __nv_bfloat16 hh[4], ll[4];
            split_bf16(a0.x, hh[0], ll[0]); split_bf16(a0.y, hh[1], ll[1]);
            split_bf16(a0.z, hh[2], ll[2]); split_bf16(a0.w, hh[3], ll[3]);
            *(uint2*)p0 = *(uint2*)hh;
            *(uint2*)(p0 + 16384) = *(uint2*)ll;
            split_bf16(a1.x, hh[0], ll[0]); split_bf16(a1.y, hh[1], ll[1]);
            split_bf16(a1.z, hh[2], ll[2]); split_bf16(a1.w, hh[3], ll[3]);
            *(uint2*)p1 = *(uint2*)hh;
            *(uint2*)(p1 + 16384) = *(uint2*)ll;
        }
    }
    __syncthreads();

    // ---- mma: 8 warps = 2(m) x 4(n); warp tile 64m x 64n ----
    const int wm = (wid & 1) * 64;
    const int wng = (wid >> 1) * 64;
    const uint32_t nhb = (uint32_t)((wng >> 7) * 16384);
    const int ncb = (wng & 127) >> 3;

    float acc[4][8][4];
#pragma unroll
    for (int i = 0; i < 4; i++)
#pragma unroll
        for (int j = 0; j < 8; j++)
#pragma unroll
            for (int q = 0; q < 4; q++) acc[i][j][q] = 0.f;

    auto compute = [&](uint32_t sah, uint32_t sal, uint32_t sbh, uint32_t sbl) {
#pragma unroll
        for (int kq = 0; kq < 4; kq++) {
            uint32_t ah[4][4], al[4][4], bh[4][4], bl[4][4];
#pragma unroll
            for (int mi = 0; mi < 4; mi++) {
                int m = wm + mi * 16 + (lane & 15);
                int kcc = kq * 2 + (lane >> 4);
                uint32_t ad = (uint32_t)(m * 128 + ((kcc ^ (m & 7)) << 4));
                LDSM4(ah[mi][0], ah[mi][1], ah[mi][2], ah[mi][3], sah + ad);
                LDSM4(al[mi][0], al[mi][1], al[mi][2], al[mi][3], sal + ad);
            }
#pragma unroll
            for (int nj = 0; nj < 4; nj++) {
                int kr = kq * 16 + (lane & 15);
                int nc = ncb + nj * 2 + (lane >> 4);
                uint32_t bd = nhb + (uint32_t)(kr * 256 + ((nc ^ (kr & 7)) << 4));
                LDSM4T(bh[nj][0], bh[nj][1], bh[nj][2], bh[nj][3], sbh + bd);
                LDSM4T(bl[nj][0], bl[nj][1], bl[nj][2], bl[nj][3], sbl + bd);
            }
#pragma unroll
            for (int mi = 0; mi < 4; mi++)
#pragma unroll
                for (int nt = 0; nt < 8; nt++) {
                    int nj = nt >> 1, pq = (nt & 1) * 2;
                    MMA_BF16(acc[mi][nt], ah[mi], bh[nj][pq], bh[nj][pq + 1]);
                    MMA_BF16(acc[mi][nt], ah[mi], bl[nj][pq], bl[nj][pq + 1]);
                    MMA_BF16(acc[mi][nt], al[mi], bh[nj][pq], bh[nj][pq + 1]);
                }
        }
    };

    // ---- phase 2a: agg chunks 0-3 (A resident in X, B single-buffered in Y) ----
    for (int c = 0; c < 4; c++) {
        if (c == 3) { CP_WAIT(1); } else { CP_WAIT(0); }
        __syncthreads();
        compute(sb + c * 32768, sb + c * 32768 + 16384, Y, Y + 32768);
        __syncthreads();
        if (c < 3) { load_B(c + 1, Y); CP_COMMIT(); }
        if (c == 2) { load_Ax0(4, sb); load_B(4, sb + 32768); CP_COMMIT(); }
        if (c == 3) { load_Ax0(5, Y);  load_B(5, Y + 32768);  CP_COMMIT(); }
    }
    // ---- phase 2b: x0 chunks 4-7, double-buffered X/Y ----
    for (int c = 4; c < 8; c++) {
        if (c < 7) { CP_WAIT(1); } else { CP_WAIT(0); }
        __syncthreads();
        uint32_t buf = (c & 1) ? Y : sb;
        compute(buf, buf + 16384, buf + 32768, buf + 65536);
        __syncthreads();
        if (c < 6) {
            int c2 = c + 2;
            uint32_t b2 = (c2 & 1) ? Y : sb;
            load_Ax0(c2, b2); load_B(c2, b2 + 32768);
            CP_COMMIT();
        }
    }

    // ---- epilogue: write h_out, LN partials ----
    float s = 0.f, ss = 0.f;
    int rbase = T * 128 + wm + (lane >> 2);
    int cbase = wng + (lane & 3) * 2;
#pragma unroll
    for (int mi = 0; mi < 4; mi++) {
        int r0 = rbase + mi * 16;
        int r1 = r0 + 8;
        bool v0 = r0 < nvalid, v1 = r1 < nvalid;
#pragma unroll
        for (int nt = 0; nt < 8; nt++) {
            int col = cbase + nt * 8;
            if (v0) {
                float2 p = make_float2(acc[mi][nt][0], acc[mi][nt][1]);
                *(float2*)&hout[(size_t)r0 * DH + col] = p;
                s += p.x + p.y; ss += p.x * p.x + p.y * p.y;
            }
            if (v1) {
                float2 p = make_float2(acc[mi][nt][2], acc[mi][nt][3]);
                *(float2*)&hout[(size_t)r1 * DH + col] = p;
                s += p.x + p.y; ss += p.x * p.x + p.y * p.y;
            }
        }
    }
    __syncthreads();
    float* red = (float*)smem;
    red[tid] = s; red[256 + tid] = ss;
    __syncthreads();
    for (int o = 128; o > 0; o >>= 1) {
        if (tid < o) { red[tid] += red[tid + o]; red[256 + tid] += red[256 + tid + o]; }
        __syncthreads();
    }
    if (tid == 0) { g_part[T] = red[0]; g_part2[T] = red[256]; }
}

// ---------------- layernorm on h_out of layer `layer` (finalize + normalize + relu) ----------------
__global__ __launch_bounds__(256) void k_norm(const float* __restrict__ gamma,
                                              const float* __restrict__ beta,
                                              int total4, int nparts, float invcnt, int layer) {
    __shared__ float sred[512];
    __shared__ float s_scale[256], s_shift[256];
    const int tid = threadIdx.x;
    float* __restrict__ hb = (layer & 1) ? g_ha : g_hb;

    float s = 0.f, ss = 0.f;
    for (int i = tid; i < nparts; i += 256) { s += g_part[i]; ss += g_part2[i]; }
    sred[tid] = s; sred[256 + tid] = ss;
    __syncthreads();
    for (int o = 128; o > 0; o >>= 1) {
        if (tid < o) { sred[tid] += sred[tid + o]; sred[256 + tid] += sred[256 + tid + o]; }
        __syncthreads();
    }
    float mu = sred[0] * invcnt;
    float var = fmaxf(sred[256] * invcnt - mu * mu, 0.f);
    float inv = 1.0f / (sqrtf(var) + 1e-5f);
    float gch = gamma[tid] * inv;
    s_scale[tid] = gch;
    s_shift[tid] = beta[tid] - mu * gch;
    __syncthreads();

    int stride = gridDim.x * 256;
    for (int i = blockIdx.x * 256 + tid; i < total4; i += stride) {
        float4 v = ((const float4*)hb)[i];
        int f = (i * 4) & 255;
        float4 g = *(float4*)&s_scale[f];
        float4 b = *(float4*)&s_shift[f];
        v.x = fmaxf(fmaf(v.x, g.x, b.x), 0.f);
        v.y = fmaxf(fmaf(v.y, g.y, b.y), 0.f);
        v.z = fmaxf(fmaf(v.z, g.z, b.z), 0.f);
        v.w = fmaxf(fmaf(v.w, g.w, b.w), 0.f);
        ((float4*)hb)[i] = v;
    }
}

// ---------------- dense f32x2 GEMM for lin1 / lin2 ----------------
__device__ __forceinline__ unsigned long long pack_dup(float x) {
    unsigned long long r; unsigned u = __float_as_uint(x);
    asm("mov.b64 %0, {%1, %1};" : "=l"(r) : "r"(u));
    return r;
}
__device__ __forceinline__ float2 unpack2(unsigned long long v) {
    unsigned lo, hi;
    asm("mov.b64 {%0, %1}, %2;" : "=r"(lo), "=r"(hi) : "l"(v));
    return make_float2(__uint_as_float(lo), __uint_as_float(hi));
}
#define FMA2(acc, a, b) asm("fma.rn.f32x2 %0, %1, %2, %0;" : "+l"(acc) : "l"(a), "l"(b))

// MODE 0: x0 = relu(x @ lin1_w + b) -> g_ha + g_xh/g_xl
// MODE 2: out = relu(norm7(g_ha) @ lin2_w + b) -> Cext (after 8 layers h lives in g_ha)
template <int MODE>
__global__ __launch_bounds__(256, 2)
void k_gemm(const float* __restrict__ Aext, const float* __restrict__ Bext,
            const float* __restrict__ bias, float* __restrict__ Cext,
            int M, int K, int ldb,
            const float* __restrict__ ngamma, const float* __restrict__ nbeta,
            int nparts, float invcnt)
{
    __shared__ float As[16][128];
    __shared__ float Bs[16][128];
    __shared__ float s_scale[256], s_shift[256];
    int tid = threadIdx.x;

    if (MODE == 2) {
        float* red = &As[0][0];
        float s = 0.f, ss = 0.f;
        for (int i = tid; i < nparts; i += 256) { s += g_part[i]; ss += g_part2[i]; }
        red[tid] = s; red[256 + tid] = ss;
        __syncthreads();
        for (int o = 128; o > 0; o >>= 1) {
            if (tid < o) { red[tid] += red[tid + o]; red[256 + tid] += red[256 + tid + o]; }
            __syncthreads();
        }
        float m = red[0] * invcnt;
        float var = fmaxf(red[256] * invcnt - m * m, 0.f);
        float inv = 1.0f / (sqrtf(var) + 1e-5f);
        float gch = ngamma[tid] * inv;
        s_scale[tid] = gch;
        s_shift[tid] = nbeta[tid] - m * gch;
        __syncthreads();
    }

    int m0 = blockIdx.x * 128, n0 = blockIdx.y * 128;
    int ty = tid >> 4, tx = tid & 15;

    int ar = tid >> 1;
    int akq = (tid & 1) * 8;
    int am = m0 + ar; if (am > M - 1) am = M - 1;
    int bk = tid >> 4;
    int bnq = (tid & 15) * 8;

    unsigned long long acc[8][4];
#pragma unroll
    for (int i = 0; i < 8; i++)
#pragma unroll
        for (int j = 0; j < 4; j++) acc[i][j] = 0ull;

    for (int k0 = 0; k0 < K; k0 += 16) {
        const float* asrc;
        if (MODE == 0) asrc = Aext + am * 128 + k0 + akq;
        else           asrc = &g_ha[(size_t)am * DH + k0 + akq];
        float4 av0 = *(const float4*)asrc;
        float4 av1 = *(const float4*)(asrc + 4);
        if (MODE == 2) {
            float4 c0 = *(float4*)&s_scale[k0 + akq];
            float4 c1 = *(float4*)&s_scale[k0 + akq + 4];
            float4 d0 = *(float4*)&s_shift[k0 + akq];
            float4 d1 = *(float4*)&s_shift[k0 + akq + 4];
            av0.x = fmaxf(fmaf(av0.x, c0.x, d0.x), 0.f);
            av0.y = fmaxf(fmaf(av0.y, c0.y, d0.y), 0.f);
            av0.z = fmaxf(fmaf(av0.z, c0.z, d0.z), 0.f);
            av0.w = fmaxf(fmaf(av0.w, c0.w, d0.w), 0.f);
            av1.x = fmaxf(fmaf(av1.x, c1.x, d1.x), 0.f);
            av1.y = fmaxf(fmaf(av1.y, c1.y, d1.y), 0.f);
            av1.z = fmaxf(fmaf(av1.z, c1.z, d1.z), 0.f);
            av1.w = fmaxf(fmaf(av1.w, c1.w, d1.w), 0.f);
        }
        const float* bsrc = Bext + (k0 + bk) * ldb + n0 + bnq;
        float4 bv0 = *(const float4*)bsrc;
        float4 bv1 = *(const float4*)(bsrc + 4);

        __syncthreads();
        As[akq + 0][ar] = av0.x; As[akq + 1][ar] = av0.y;
        As[akq + 2][ar] = av0.z; As[akq + 3][ar] = av0.w;
        As[akq + 4][ar] = av1.x; As[akq + 5][ar] = av1.y;
        As[akq + 6][ar] = av1.z; As[akq + 7][ar] = av1.w;
        *(float4*)&Bs[bk][bnq] = bv0;
        *(float4*)&Bs[bk][bnq + 4] = bv1;
        __syncthreads();

#pragma unroll
        for (int kk = 0; kk < 16; kk++) {
            float4 aA = *(const float4*)&As[kk][ty * 8];
            float4 aB = *(const float4*)&As[kk][ty * 8 + 4];
            ulonglong2 bb0 = *(const ulonglong2*)&Bs[kk][tx * 4];
            ulonglong2 bb1 = *(const ulonglong2*)&Bs[kk][64 + tx * 4];
            unsigned long long ad[8];
            ad[0] = pack_dup(aA.x); ad[1] = pack_dup(aA.y);
            ad[2] = pack_dup(aA.z); ad[3] = pack_dup(aA.w);
            ad[4] = pack_dup(aB.x); ad[5] = pack_dup(aB.y);
            ad[6] = pack_dup(aB.z); ad[7] = pack_dup(aB.w);
#pragma unroll
            for (int i = 0; i < 8; i++) {
                FMA2(acc[i][0], ad[i], bb0.x);
                FMA2(acc[i][1], ad[i], bb0.y);
                FMA2(acc[i][2], ad[i], bb1.x);
                FMA2(acc[i][3], ad[i], bb1.y);
            }
        }
    }

    int nA = n0 + tx * 4;
    int nB = n0 + 64 + tx * 4;
    float4 biasA = *(const float4*)&bias[nA];
    float4 biasB = *(const float4*)&bias[nB];

#pragma unroll
    for (int i = 0; i < 8; i++) {
        int m = m0 + ty * 8 + i;
        if (m >= M) continue;
        float2 p0 = unpack2(acc[i][0]), p1 = unpack2(acc[i][1]);
        float2 p2 = unpack2(acc[i][2]), p3 = unpack2(acc[i][3]);
        float4 vA = make_float4(fmaxf(p0.x + biasA.x, 0.f), fmaxf(p0.y + biasA.y, 0.f),
                                fmaxf(p1.x + biasA.z, 0.f), fmaxf(p1.y + biasA.w, 0.f));
        float4 vB = make_float4(fmaxf(p2.x + biasB.x, 0.f), fmaxf(p2.y + biasB.y, 0.f),
                                fmaxf(p3.x + biasB.z, 0.f), fmaxf(p3.y + biasB.w, 0.f));

        if (MODE == 0) {
            size_t o = (size_t)m * DH;
            *(float4*)&g_ha[o + nA] = vA;
            *(float4*)&g_ha[o + nB] = vB;
            size_t ro = (size_t)m * 256;
            __nv_bfloat16 h_[4], l_[4];
            split_bf16(vA.x, h_[0], l_[0]); split_bf16(vA.y, h_[1], l_[1]);
            split_bf16(vA.z, h_[2], l_[2]); split_bf16(vA.w, h_[3], l_[3]);
            *(uint2*)&g_xh[ro + nA] = *(uint2*)h_;
            *(uint2*)&g_xl[ro + nA] = *(uint2*)l_;
            split_bf16(vB.x, h_[0], l_[0]); split_bf16(vB.y, h_[1], l_[1]);
            split_bf16(vB.z, h_[2], l_[2]); split_bf16(vB.w, h_[3], l_[3]);
            *(uint2*)&g_xh[ro + nB] = *(uint2*)h_;
            *(uint2*)&g_xl[ro + nB] = *(uint2*)l_;
        } else {
            size_t o = (size_t)m * 128;
            *(float4*)&Cext[o + nA] = vA;
            *(float4*)&Cext[o + nB] = vB;
        }
    }
}

// ---------------- launch ----------------
extern "C" void kernel_launch(void* const* d_in, const int* in_sizes, int n_in,
                              void* d_out, int out_size) {
    const float* x      = (const float*)d_in[0];
    const int*   ei     = (const int*)d_in[1];
    const float* lin1_w = (const float*)d_in[2];
    const float* lin1_b = (const float*)d_in[3];
    const float* w1     = (const float*)d_in[4];
    const float* w2     = (const float*)d_in[5];
    const float* gamma  = (const float*)d_in[6];
    const float* betab  = (const float*)d_in[7];
    const float* lin2_w = (const float*)d_in[8];
    const float* lin2_b = (const float*)d_in[9];
    float* out = (float*)d_out;

    int N = in_sizes[0] / 128;
    int E = in_sizes[1] / 2;
    const int* row = ei;
    const int* col = ei + E;

    int Mt = (N + 127) / 128;
    int total4 = N * (DH / 4);
    float invcnt = 1.0f / ((float)N * (float)DH);

    static int smem_set = 0;
    if (!smem_set) {
        cudaFuncSetAttribute(k_fused, cudaFuncAttributeMaxDynamicSharedMemorySize, SMTOT);
        smem_set = 1;
    }

    k_init<<<(N + 255) / 256, 256>>>(N);
    k_count<<<(E + 255) / 256, 256>>>(col, E);
    k_scan<<<1, 1024>>>(N, E);
    k_scatter<<<(E + 255) / 256, 256>>>(row, col, E);
    k_prep_b<<<(NL * 512 * 256 + 255) / 256, 256>>>(w1, w2);

    // x0 = relu(x @ lin1_w + b) -> g_ha + g_xh/g_xl
    k_gemm<0><<<dim3(Mt, 2), 256>>>(x, lin1_w, lin1_b, nullptr, N, 128, 256,
                                    nullptr, nullptr, 0, 0.f);

    for (int l = 0; l < NL; l++) {
        k_fused<<<Mt, 256, SMTOT>>>(l, N);
        if (l < NL - 1) {
            k_norm<<<1184, 256>>>(gamma + l * DH, betab + l * DH, total4, Mt, invcnt, l);
        }
    }

    // after layer 7 (odd), h_out is g_ha; out = relu(norm7(g_ha) @ lin2_w + b)
    k_gemm<2><<<dim3(Mt, 1), 256>>>(nullptr, lin2_w, lin2_b, out, N, 256, 128,
                                    gamma + 7 * DH, betab + 7 * DH, Mt, invcnt);
}

// round 9
// speedup vs baseline: 1.4282x; 1.4282x over previous
#include <cuda_runtime.h>
#include <cuda_bf16.h>
#include <math.h>
#include <stdint.h>

#define NN 50000
#define EE 800000
#define DH 256
#define NL 8
#define NTILES ((NN + 127) / 128)
#define NPAD (NTILES * 128)

// ---------------- scratch ----------------
__device__ float g_ha[NN * DH];   // h ping
__device__ float g_hb[NN * DH];   // h pong
__device__ __align__(16) __nv_bfloat16 g_ahh[(size_t)NPAD * 512];  // A hi [node][k] k<256 agg, k>=256 x0
__device__ __align__(16) __nv_bfloat16 g_all[(size_t)NPAD * 512];  // A lo
__device__ __align__(16) __nv_bfloat16 g_bhh[(size_t)NL * 512 * 256];
__device__ __align__(16) __nv_bfloat16 g_bll[(size_t)NL * 512 * 256];
__device__ float g_dis[NN];
__device__ int   g_counts[NN];
__device__ int   g_cursor[NN];
__device__ int   g_rowptr[NN + 1];
__device__ int   g_csr[EE];
__device__ float g_part[NTILES + 8];
__device__ float g_part2[NTILES + 8];

// ---------------- helpers ----------------
__device__ __forceinline__ uint32_t s2u(const void* p) {
    uint32_t a;
    asm("{ .reg .u64 t; cvta.to.shared.u64 t, %1; cvt.u32.u64 %0, t; }" : "=r"(a) : "l"(p));
    return a;
}
__device__ __forceinline__ unsigned long long pack_dup(float x) {
    unsigned long long r; unsigned u = __float_as_uint(x);
    asm("mov.b64 %0, {%1, %1};" : "=l"(r) : "r"(u));
    return r;
}
__device__ __forceinline__ float2 unpack2(unsigned long long v) {
    unsigned lo, hi;
    asm("mov.b64 {%0, %1}, %2;" : "=r"(lo), "=r"(hi) : "l"(v));
    return make_float2(__uint_as_float(lo), __uint_as_float(hi));
}
#define FMA2(acc, a, b) asm("fma.rn.f32x2 %0, %1, %2, %0;" : "+l"(acc) : "l"(a), "l"(b))

__device__ __forceinline__ void cp16(uint32_t dst, const void* src) {
    asm volatile("cp.async.cg.shared.global [%0], [%1], 16;" :: "r"(dst), "l"(src) : "memory");
}
#define CP_COMMIT() asm volatile("cp.async.commit_group;" ::: "memory")
#define CP_WAIT(n)  asm volatile("cp.async.wait_group %0;" :: "n"(n) : "memory")

#define LDSM4(r0,r1,r2,r3,a) \
    asm volatile("ldmatrix.sync.aligned.m8n8.x4.shared.b16 {%0,%1,%2,%3}, [%4];" \
                 : "=r"(r0),"=r"(r1),"=r"(r2),"=r"(r3) : "r"(a))
#define LDSM4T(r0,r1,r2,r3,a) \
    asm volatile("ldmatrix.sync.aligned.m8n8.x4.trans.shared.b16 {%0,%1,%2,%3}, [%4];" \
                 : "=r"(r0),"=r"(r1),"=r"(r2),"=r"(r3) : "r"(a))
#define MMA_BF16(c,a,b0,b1) \
    asm volatile("mma.sync.aligned.m16n8k16.row.col.f32.bf16.bf16.f32 " \
                 "{%0,%1,%2,%3}, {%4,%5,%6,%7}, {%8,%9}, {%0,%1,%2,%3};" \
                 : "+f"((c)[0]),"+f"((c)[1]),"+f"((c)[2]),"+f"((c)[3]) \
                 : "r"((a)[0]),"r"((a)[1]),"r"((a)[2]),"r"((a)[3]),"r"(b0),"r"(b1))

__device__ __forceinline__ void split_bf16(float v, __nv_bfloat16& h, __nv_bfloat16& l) {
    h = __float2bfloat16_rn(v);
    l = __float2bfloat16_rn(v - __bfloat162float(h));
}

// ---------------- graph preprocessing ----------------
__global__ void k_init(int n) {
    int i = blockIdx.x * blockDim.x + threadIdx.x;
    if (i < n) { g_counts[i] = 0; g_cursor[i] = 0; }
}
__global__ void k_count(const int* __restrict__ col, int E) {
    int e = blockIdx.x * blockDim.x + threadIdx.x;
    if (e < E) atomicAdd(&g_counts[col[e]], 1);
}
__global__ void k_scan(int n, int E) {
    __shared__ int sh[1024];
    int tid = threadIdx.x;
    int C = (n + 1023) >> 10;
    int base = tid * C;
    int s = 0;
    for (int i = 0; i < C; i++) { int idx = base + i; if (idx < n) s += g_counts[idx]; }
    sh[tid] = s; __syncthreads();
    for (int off = 1; off < 1024; off <<= 1) {
        int v = (tid >= off) ? sh[tid - off] : 0;
        __syncthreads();
        sh[tid] += v;
        __syncthreads();
    }
    int run = (tid > 0) ? sh[tid - 1] : 0;
    for (int i = 0; i < C; i++) {
        int idx = base + i;
        if (idx < n) {
            g_rowptr[idx] = run;
            int c = g_counts[idx];
            run += c;
            g_dis[idx] = rsqrtf((float)(c + 1));
        }
    }
    if (tid == 0) g_rowptr[n] = E;
}
__global__ void k_scatter(const int* __restrict__ row, const int* __restrict__ col, int E) {
    int e = blockIdx.x * blockDim.x + threadIdx.x;
    if (e < E) {
        int c = col[e];
        int p = g_rowptr[c] + atomicAdd(&g_cursor[c], 1);
        g_csr[p] = row[e];
    }
}

// ---------------- B' prep ----------------
__global__ void k_prep_b(const float* __restrict__ w1, const float* __restrict__ w2) {
    int idx = blockIdx.x * blockDim.x + threadIdx.x;
    if (idx >= NL * 512 * 256) return;
    int n = idx & 255;
    int k = (idx >> 8) & 511;
    int l = idx >> 17;
    float beta = logf(1.0f / (float)(l + 1) + 1.0f);
    float v = (k < 256) ? w1[(l << 16) + (k << 8) + n]
                        : w2[(l << 16) + ((k - 256) << 8) + n];
    float val = 0.5f * beta * v;
    if (k == n || k == n + 256) val += 0.5f * (1.0f - beta);
    __nv_bfloat16 h, lo; split_bf16(val, h, lo);
    g_bhh[idx] = h;
    g_bll[idx] = lo;
}

// ---------------- CSR gather (f32x2) -> bf16 hi/lo A rows (k 0..255) ----------------
__global__ __launch_bounds__(256) void k_gather(int layer, int n) {
    int w = (blockIdx.x * blockDim.x + threadIdx.x) >> 5;
    int lane = threadIdx.x & 31;
    if (w >= n) return;
    const float* __restrict__ hin = (layer & 1) ? g_hb : g_ha;
    const ulonglong2* __restrict__ h2 = (const ulonglong2*)hin;
    float dc = g_dis[w];
    int base = w * 64;
    unsigned long long acc0 = 0, acc1 = 0, acc2 = 0, acc3 = 0;
    {
        unsigned long long d = pack_dup(dc);
        ulonglong2 v0 = h2[base + lane], v1 = h2[base + 32 + lane];
        FMA2(acc0, d, v0.x); FMA2(acc1, d, v0.y);
        FMA2(acc2, d, v1.x); FMA2(acc3, d, v1.y);
    }
    int beg = g_rowptr[w], end = g_rowptr[w + 1];
    int i = beg;
    for (; i + 3 < end; i += 4) {
        int s0 = g_csr[i], s1 = g_csr[i + 1], s2 = g_csr[i + 2], s3 = g_csr[i + 3];
        unsigned long long w0 = pack_dup(g_dis[s0]), w1 = pack_dup(g_dis[s1]);
        unsigned long long w2 = pack_dup(g_dis[s2]), w3 = pack_dup(g_dis[s3]);
        ulonglong2 p0 = h2[s0 * 64 + lane], p1 = h2[s0 * 64 + 32 + lane];
        ulonglong2 q0 = h2[s1 * 64 + lane], q1 = h2[s1 * 64 + 32 + lane];
        ulonglong2 r0 = h2[s2 * 64 + lane], r1 = h2[s2 * 64 + 32 + lane];
        ulonglong2 t0 = h2[s3 * 64 + lane], t1 = h2[s3 * 64 + 32 + lane];
        FMA2(acc0, w0, p0.x); FMA2(acc1, w0, p0.y); FMA2(acc2, w0, p1.x); FMA2(acc3, w0, p1.y);
        FMA2(acc0, w1, q0.x); FMA2(acc1, w1, q0.y); FMA2(acc2, w1, q1.x); FMA2(acc3, w1, q1.y);
        FMA2(acc0, w2, r0.x); FMA2(acc1, w2, r0.y); FMA2(acc2, w2, r1.x); FMA2(acc3, w2, r1.y);
        FMA2(acc0, w3, t0.x); FMA2(acc1, w3, t0.y); FMA2(acc2, w3, t1.x); FMA2(acc3, w3, t1.y);
    }
    for (; i < end; i++) {
        int s0 = g_csr[i];
        unsigned long long w0 = pack_dup(g_dis[s0]);
        ulonglong2 p0 = h2[s0 * 64 + lane], p1 = h2[s0 * 64 + 32 + lane];
        FMA2(acc0, w0, p0.x); FMA2(acc1, w0, p0.y); FMA2(acc2, w0, p1.x); FMA2(acc3, w0, p1.y);
    }
    float2 f0 = unpack2(acc0), f1 = unpack2(acc1), f2 = unpack2(acc2), f3 = unpack2(acc3);
    float4 a0 = make_float4(f0.x * dc, f0.y * dc, f1.x * dc, f1.y * dc);
    float4 a1 = make_float4(f2.x * dc, f2.y * dc, f3.x * dc, f3.y * dc);

    __nv_bfloat16 h_[4], l_[4];
    size_t ro = (size_t)w * 512;
    split_bf16(a0.x, h_[0], l_[0]); split_bf16(a0.y, h_[1], l_[1]);
    split_bf16(a0.z, h_[2], l_[2]); split_bf16(a0.w, h_[3], l_[3]);
    *(uint2*)&g_ahh[ro + lane * 4] = *(uint2*)h_;
    *(uint2*)&g_all[ro + lane * 4] = *(uint2*)l_;
    split_bf16(a1.x, h_[0], l_[0]); split_bf16(a1.y, h_[1], l_[1]);
    split_bf16(a1.z, h_[2], l_[2]); split_bf16(a1.w, h_[3], l_[3]);
    *(uint2*)&g_ahh[ro + 128 + lane * 4] = *(uint2*)h_;
    *(uint2*)&g_all[ro + 128 + lane * 4] = *(uint2*)l_;
}

// ---------------- bf16 3-pass tensor GEMM, 128m x 256n CTA, K=512 (8x64 chunks) ----------------
// 8 warps = 2(m) x 4(n), warp tile 64x64. smem stage = A(hi16K+lo16K) + B(hi32K+lo32K) = 96KB, x2.
#define STAGE 98304u
#define SMTOT 196608
__global__ __launch_bounds__(256, 1) void k_mma(int layer, int nvalid) {
    extern __shared__ char smem[];
    uint32_t sb = s2u(smem);
    const int tid = threadIdx.x, lane = tid & 31, wid = tid >> 5;
    const int T = blockIdx.x;

    float* __restrict__ hout = (layer & 1) ? g_ha : g_hb;

    const __nv_bfloat16* __restrict__ Agh = g_ahh + (size_t)T * 128 * 512;
    const __nv_bfloat16* __restrict__ Agl = g_all + (size_t)T * 128 * 512;
    const __nv_bfloat16* __restrict__ Bgh = g_bhh + (size_t)layer * 512 * 256;
    const __nv_bfloat16* __restrict__ Bgl = g_bll + (size_t)layer * 512 * 256;

    auto load_chunk = [&](int c, int st) {
        uint32_t s0 = sb + st * STAGE;
        // A hi/lo: 1024 x 16B each
#pragma unroll
        for (int i = 0; i < 4; i++) {
            int e = tid + i * 256;
            int m = e >> 3, kc = e & 7;
            uint32_t da = (uint32_t)(m * 128 + ((kc ^ (m & 7)) << 4));
            cp16(s0 + da, Agh + (size_t)m * 512 + c * 64 + kc * 8);
            cp16(s0 + 16384 + da, Agl + (size_t)m * 512 + c * 64 + kc * 8);
        }
        // B hi/lo: 2048 x 16B each, two 16KB n-halves
#pragma unroll
        for (int i = 0; i < 8; i++) {
            int e = tid + i * 256;
            int k = e >> 5, ncol = e & 31;
            int nhalf = ncol >> 4, nc = ncol & 15;
            uint32_t db = (uint32_t)(nhalf * 16384 + k * 256 + ((nc ^ (k & 7)) << 4));
            size_t src = (size_t)(c * 64 + k) * 256 + nhalf * 128 + nc * 8;
            cp16(s0 + 32768 + db, Bgh + src);
            cp16(s0 + 65536 + db, Bgl + src);
        }
        CP_COMMIT();
    };

    float acc[4][8][4];
#pragma unroll
    for (int i = 0; i < 4; i++)
#pragma unroll
        for (int j = 0; j < 8; j++)
#pragma unroll
            for (int q = 0; q < 4; q++) acc[i][j][q] = 0.f;

    const int wm = (wid & 1) * 64;
    const int wng = (wid >> 1) * 64;
    const uint32_t nhb = (uint32_t)((wng >> 7) * 16384);
    const int ncb = (wng & 127) >> 3;

    auto compute = [&](uint32_t s0) {
        uint32_t sah = s0, sal = s0 + 16384, sbh = s0 + 32768, sbl = s0 + 65536;
#pragma unroll
        for (int kq = 0; kq < 4; kq++) {
            uint32_t ah[4][4], al[4][4], bh[4][4], bl[4][4];
#pragma unroll
            for (int mi = 0; mi < 4; mi++) {
                int m = wm + mi * 16 + (lane & 15);
                int kcc = kq * 2 + (lane >> 4);
                uint32_t ad = (uint32_t)(m * 128 + ((kcc ^ (m & 7)) << 4));
                LDSM4(ah[mi][0], ah[mi][1], ah[mi][2], ah[mi][3], sah + ad);
                LDSM4(al[mi][0], al[mi][1], al[mi][2], al[mi][3], sal + ad);
            }
#pragma unroll
            for (int nj = 0; nj < 4; nj++) {
                int kr = kq * 16 + (lane & 15);
                int nc = ncb + nj * 2 + (lane >> 4);
                uint32_t bd = nhb + (uint32_t)(kr * 256 + ((nc ^ (kr & 7)) << 4));
                LDSM4T(bh[nj][0], bh[nj][1], bh[nj][2], bh[nj][3], sbh + bd);
                LDSM4T(bl[nj][0], bl[nj][1], bl[nj][2], bl[nj][3], sbl + bd);
            }
#pragma unroll
            for (int mi = 0; mi < 4; mi++)
#pragma unroll
                for (int nt = 0; nt < 8; nt++) {
                    int nj = nt >> 1, pq = (nt & 1) * 2;
                    MMA_BF16(acc[mi][nt], ah[mi], bh[nj][pq], bh[nj][pq + 1]);
                    MMA_BF16(acc[mi][nt], ah[mi], bl[nj][pq], bl[nj][pq + 1]);
                    MMA_BF16(acc[mi][nt], al[mi], bh[nj][pq], bh[nj][pq + 1]);
                }
        }
    };

    load_chunk(0, 0);
    for (int ch = 0; ch < 8; ch++) {
        if (ch < 7) { load_chunk(ch + 1, (ch + 1) & 1); CP_WAIT(1); }
        else        { CP_WAIT(0); }
        __syncthreads();
        compute(sb + (ch & 1) * STAGE);
        __syncthreads();
    }

    // ---- epilogue: write h_out, LN partials ----
    float s = 0.f, ss = 0.f;
    int rbase = T * 128 + wm + (lane >> 2);
    int cbase = wng + (lane & 3) * 2;
#pragma unroll
    for (int mi = 0; mi < 4; mi++) {
        int r0 = rbase + mi * 16;
        int r1 = r0 + 8;
        bool v0 = r0 < nvalid, v1 = r1 < nvalid;
#pragma unroll
        for (int nt = 0; nt < 8; nt++) {
            int col = cbase + nt * 8;
            if (v0) {
                float2 p = make_float2(acc[mi][nt][0], acc[mi][nt][1]);
                *(float2*)&hout[(size_t)r0 * DH + col] = p;
                s += p.x + p.y; ss += p.x * p.x + p.y * p.y;
            }
            if (v1) {
                float2 p = make_float2(acc[mi][nt][2], acc[mi][nt][3]);
                *(float2*)&hout[(size_t)r1 * DH + col] = p;
                s += p.x + p.y; ss += p.x * p.x + p.y * p.y;
            }
        }
    }
    __syncthreads();
    float* red = (float*)smem;
    red[tid] = s; red[256 + tid] = ss;
    __syncthreads();
    for (int o = 128; o > 0; o >>= 1) {
        if (tid < o) { red[tid] += red[tid + o]; red[256 + tid] += red[256 + tid + o]; }
        __syncthreads();
    }
    if (tid == 0) { g_part[T] = red[0]; g_part2[T] = red[256]; }
}

// ---------------- layernorm on h_out of layer `layer` ----------------
__global__ __launch_bounds__(256) void k_norm(const float* __restrict__ gamma,
                                              const float* __restrict__ beta,
                                              int total4, int nparts, float invcnt, int layer) {
    __shared__ float sred[512];
    __shared__ float s_scale[256], s_shift[256];
    const int tid = threadIdx.x;
    float* __restrict__ hb = (layer & 1) ? g_ha : g_hb;

    float s = 0.f, ss = 0.f;
    for (int i = tid; i < nparts; i += 256) { s += g_part[i]; ss += g_part2[i]; }
    sred[tid] = s; sred[256 + tid] = ss;
    __syncthreads();
    for (int o = 128; o > 0; o >>= 1) {
        if (tid < o) { sred[tid] += sred[tid + o]; sred[256 + tid] += sred[256 + tid + o]; }
        __syncthreads();
    }
    float mu = sred[0] * invcnt;
    float var = fmaxf(sred[256] * invcnt - mu * mu, 0.f);
    float inv = 1.0f / (sqrtf(var) + 1e-5f);
    float gch = gamma[tid] * inv;
    s_scale[tid] = gch;
    s_shift[tid] = beta[tid] - mu * gch;
    __syncthreads();

    int stride = gridDim.x * 256;
    for (int i = blockIdx.x * 256 + tid; i < total4; i += stride) {
        float4 v = ((const float4*)hb)[i];
        int f = (i * 4) & 255;
        float4 g = *(float4*)&s_scale[f];
        float4 b = *(float4*)&s_shift[f];
        v.x = fmaxf(fmaf(v.x, g.x, b.x), 0.f);
        v.y = fmaxf(fmaf(v.y, g.y, b.y), 0.f);
        v.z = fmaxf(fmaf(v.z, g.z, b.z), 0.f);
        v.w = fmaxf(fmaf(v.w, g.w, b.w), 0.f);
        ((float4*)hb)[i] = v;
    }
}

// ---------------- dense f32x2 GEMM for lin1 / lin2 ----------------
// MODE 0: x0 = relu(x @ lin1_w + b) -> g_ha + g_ahh/g_all (k 256..511)
// MODE 2: out = relu(norm7(g_ha) @ lin2_w + b) -> Cext
template <int MODE>
__global__ __launch_bounds__(256, 2)
void k_gemm(const float* __restrict__ Aext, const float* __restrict__ Bext,
            const float* __restrict__ bias, float* __restrict__ Cext,
            int M, int K, int ldb,
            const float* __restrict__ ngamma, const float* __restrict__ nbeta,
            int nparts, float invcnt)
{
    __shared__ float As[16][128];
    __shared__ float Bs[16][128];
    __shared__ float s_scale[256], s_shift[256];
    int tid = threadIdx.x;

    if (MODE == 2) {
        float* red = &As[0][0];
        float s = 0.f, ss = 0.f;
        for (int i = tid; i < nparts; i += 256) { s += g_part[i]; ss += g_part2[i]; }
        red[tid] = s; red[256 + tid] = ss;
        __syncthreads();
        for (int o = 128; o > 0; o >>= 1) {
            if (tid < o) { red[tid] += red[tid + o]; red[256 + tid] += red[256 + tid + o]; }
            __syncthreads();
        }
        float m = red[0] * invcnt;
        float var = fmaxf(red[256] * invcnt - m * m, 0.f);
        float inv = 1.0f / (sqrtf(var) + 1e-5f);
        float gch = ngamma[tid] * inv;
        s_scale[tid] = gch;
        s_shift[tid] = nbeta[tid] - m * gch;
        __syncthreads();
    }

    int m0 = blockIdx.x * 128, n0 = blockIdx.y * 128;
    int ty = tid >> 4, tx = tid & 15;

    int ar = tid >> 1;
    int akq = (tid & 1) * 8;
    int am = m0 + ar; if (am > M - 1) am = M - 1;
    int bk = tid >> 4;
    int bnq = (tid & 15) * 8;

    unsigned long long acc[8][4];
#pragma unroll
    for (int i = 0; i < 8; i++)
#pragma unroll
        for (int j = 0; j < 4; j++) acc[i][j] = 0ull;

    for (int k0 = 0; k0 < K; k0 += 16) {
        const float* asrc;
        if (MODE == 0) asrc = Aext + am * 128 + k0 + akq;
        else           asrc = &g_ha[(size_t)am * DH + k0 + akq];
        float4 av0 = *(const float4*)asrc;
        float4 av1 = *(const float4*)(asrc + 4);
        if (MODE == 2) {
            float4 c0 = *(float4*)&s_scale[k0 + akq];
            float4 c1 = *(float4*)&s_scale[k0 + akq + 4];
            float4 d0 = *(float4*)&s_shift[k0 + akq];
            float4 d1 = *(float4*)&s_shift[k0 + akq + 4];
            av0.x = fmaxf(fmaf(av0.x, c0.x, d0.x), 0.f);
            av0.y = fmaxf(fmaf(av0.y, c0.y, d0.y), 0.f);
            av0.z = fmaxf(fmaf(av0.z, c0.z, d0.z), 0.f);
            av0.w = fmaxf(fmaf(av0.w, c0.w, d0.w), 0.f);
            av1.x = fmaxf(fmaf(av1.x, c1.x, d1.x), 0.f);
            av1.y = fmaxf(fmaf(av1.y, c1.y, d1.y), 0.f);
            av1.z = fmaxf(fmaf(av1.z, c1.z, d1.z), 0.f);
            av1.w = fmaxf(fmaf(av1.w, c1.w, d1.w), 0.f);
        }
        const float* bsrc = Bext + (k0 + bk) * ldb + n0 + bnq;
        float4 bv0 = *(const float4*)bsrc;
        float4 bv1 = *(const float4*)(bsrc + 4);

        __syncthreads();
        As[akq + 0][ar] = av0.x; As[akq + 1][ar] = av0.y;
        As[akq + 2][ar] = av0.z; As[akq + 3][ar] = av0.w;
        As[akq + 4][ar] = av1.x; As[akq + 5][ar] = av1.y;
        As[akq + 6][ar] = av1.z; As[akq + 7][ar] = av1.w;
        *(float4*)&Bs[bk][bnq] = bv0;
        *(float4*)&Bs[bk][bnq + 4] = bv1;
        __syncthreads();

#pragma unroll
        for (int kk = 0; kk < 16; kk++) {
            float4 aA = *(const float4*)&As[kk][ty * 8];
            float4 aB = *(const float4*)&As[kk][ty * 8 + 4];
            ulonglong2 bb0 = *(const ulonglong2*)&Bs[kk][tx * 4];
            ulonglong2 bb1 = *(const ulonglong2*)&Bs[kk][64 + tx * 4];
            unsigned long long ad[8];
            ad[0] = pack_dup(aA.x); ad[1] = pack_dup(aA.y);
            ad[2] = pack_dup(aA.z); ad[3] = pack_dup(aA.w);
            ad[4] = pack_dup(aB.x); ad[5] = pack_dup(aB.y);
            ad[6] = pack_dup(aB.z); ad[7] = pack_dup(aB.w);
#pragma unroll
            for (int i = 0; i < 8; i++) {
                FMA2(acc[i][0], ad[i], bb0.x);
                FMA2(acc[i][1], ad[i], bb0.y);
                FMA2(acc[i][2], ad[i], bb1.x);
                FMA2(acc[i][3], ad[i], bb1.y);
            }
        }
    }

    int nA = n0 + tx * 4;
    int nB = n0 + 64 + tx * 4;
    float4 biasA = *(const float4*)&bias[nA];
    float4 biasB = *(const float4*)&bias[nB];

#pragma unroll
    for (int i = 0; i < 8; i++) {
        int m = m0 + ty * 8 + i;
        if (m >= M) continue;
        float2 p0 = unpack2(acc[i][0]), p1 = unpack2(acc[i][1]);
        float2 p2 = unpack2(acc[i][2]), p3 = unpack2(acc[i][3]);
        float4 vA = make_float4(fmaxf(p0.x + biasA.x, 0.f), fmaxf(p0.y + biasA.y, 0.f),
                                fmaxf(p1.x + biasA.z, 0.f), fmaxf(p1.y + biasA.w, 0.f));
        float4 vB = make_float4(fmaxf(p2.x + biasB.x, 0.f), fmaxf(p2.y + biasB.y, 0.f),
                                fmaxf(p3.x + biasB.z, 0.f), fmaxf(p3.y + biasB.w, 0.f));

        if (MODE == 0) {
            size_t o = (size_t)m * DH;
            *(float4*)&g_ha[o + nA] = vA;
            *(float4*)&g_ha[o + nB] = vB;
            size_t ro = (size_t)m * 512 + 256;
            __nv_bfloat16 h_[4], l_[4];
            split_bf16(vA.x, h_[0], l_[0]); split_bf16(vA.y, h_[1], l_[1]);
            split_bf16(vA.z, h_[2], l_[2]); split_bf16(vA.w, h_[3], l_[3]);
            *(uint2*)&g_ahh[ro + nA] = *(uint2*)h_;
            *(uint2*)&g_all[ro + nA] = *(uint2*)l_;
            split_bf16(vB.x, h_[0], l_[0]); split_bf16(vB.y, h_[1], l_[1]);
            split_bf16(vB.z, h_[2], l_[2]); split_bf16(vB.w, h_[3], l_[3]);
            *(uint2*)&g_ahh[ro + nB] = *(uint2*)h_;
            *(uint2*)&g_all[ro + nB] = *(uint2*)l_;
        } else {
            size_t o = (size_t)m * 128;
            *(float4*)&Cext[o + nA] = vA;
            *(float4*)&Cext[o + nB] = vB;
        }
    }
}

// ---------------- launch (single stream) ----------------
extern "C" void kernel_launch(void* const* d_in, const int* in_sizes, int n_in,
                              void* d_out, int out_size) {
    const float* x      = (const float*)d_in[0];
    const int*   ei     = (const int*)d_in[1];
    const float* lin1_w = (const float*)d_in[2];
    const float* lin1_b = (const float*)d_in[3];
    const float* w1     = (const float*)d_in[4];
    const float* w2     = (const float*)d_in[5];
    const float* gamma  = (const float*)d_in[6];
    const float* betab  = (const float*)d_in[7];
    const float* lin2_w = (const float*)d_in[8];
    const float* lin2_b = (const float*)d_in[9];
    float* out = (float*)d_out;

    int N = in_sizes[0] / 128;
    int E = in_sizes[1] / 2;
    const int* row = ei;
    const int* col = ei + E;

    int Mt = (N + 127) / 128;
    int total4 = N * (DH / 4);
    float invcnt = 1.0f / ((float)N * (float)DH);

    static int smem_set = 0;
    if (!smem_set) {
        cudaFuncSetAttribute(k_mma, cudaFuncAttributeMaxDynamicSharedMemorySize, SMTOT);
        smem_set = 1;
    }

    k_init<<<(N + 255) / 256, 256>>>(N);
    k_count<<<(E + 255) / 256, 256>>>(col, E);
    k_scan<<<1, 1024>>>(N, E);
    k_scatter<<<(E + 255) / 256, 256>>>(row, col, E);
    k_prep_b<<<(NL * 512 * 256 + 255) / 256, 256>>>(w1, w2);

    // x0 = relu(x @ lin1_w + b) -> g_ha + g_ahh/g_all upper-k
    k_gemm<0><<<dim3(Mt, 2), 256>>>(x, lin1_w, lin1_b, nullptr, N, 128, 256,
                                    nullptr, nullptr, 0, 0.f);

    for (int l = 0; l < NL; l++) {
        k_gather<<<(N * 32 + 255) / 256, 256>>>(l, N);
        k_mma<<<Mt, 256, SMTOT>>>(l, N);
        if (l < NL - 1)
            k_norm<<<1184, 256>>>(gamma + l * DH, betab + l * DH, total4, Mt, invcnt, l);
    }

    // after layer 7 (odd) h lives in g_ha; out = relu(norm7(g_ha) @ lin2_w + b)
    k_gemm<2><<<dim3(Mt, 1), 256>>>(nullptr, lin2_w, lin2_b, out, N, 256, 128,
                                    gamma + 7 * DH, betab + 7 * DH, Mt, invcnt);
}

// round 10
// speedup vs baseline: 1.5120x; 1.0587x over previous
#include <cuda_runtime.h>
#include <cuda_bf16.h>
#include <cuda_fp16.h>
#include <math.h>
#include <stdint.h>

#define NN 50000
#define EE 800000
#define DH 256
#define NL 8
#define NTILES ((NN + 127) / 128)
#define NPAD (NTILES * 128)

// ---------------- scratch ----------------
__device__ float g_ha[NN * DH];                                     // fp32 h_out (per-layer, overwritten)
__device__ __align__(16) __half g_hn[(size_t)NN * DH];              // fp16 gather operand: relu(norm(h)) / x0
__device__ __align__(16) __nv_bfloat16 g_ahh[(size_t)NPAD * 512];   // A hi [node][k] k<256 agg, k>=256 x0
__device__ __align__(16) __nv_bfloat16 g_all[(size_t)NPAD * 512];   // A lo
__device__ __align__(16) __nv_bfloat16 g_bhh[(size_t)NL * 512 * 256];
__device__ __align__(16) __nv_bfloat16 g_bll[(size_t)NL * 512 * 256];
__device__ float g_dis[NN];
__device__ int   g_counts[NN];
__device__ int   g_cursor[NN];
__device__ int   g_rowptr[NN + 1];
__device__ int   g_csr[EE];
__device__ float g_part[NTILES + 8];
__device__ float g_part2[NTILES + 8];

// ---------------- helpers ----------------
__device__ __forceinline__ uint32_t s2u(const void* p) {
    uint32_t a;
    asm("{ .reg .u64 t; cvta.to.shared.u64 t, %1; cvt.u32.u64 %0, t; }" : "=r"(a) : "l"(p));
    return a;
}
__device__ __forceinline__ unsigned long long pack_dup(float x) {
    unsigned long long r; unsigned u = __float_as_uint(x);
    asm("mov.b64 %0, {%1, %1};" : "=l"(r) : "r"(u));
    return r;
}
__device__ __forceinline__ float2 unpack2(unsigned long long v) {
    unsigned lo, hi;
    asm("mov.b64 {%0, %1}, %2;" : "=r"(lo), "=r"(hi) : "l"(v));
    return make_float2(__uint_as_float(lo), __uint_as_float(hi));
}
#define FMA2(acc, a, b) asm("fma.rn.f32x2 %0, %1, %2, %0;" : "+l"(acc) : "l"(a), "l"(b))

__device__ __forceinline__ void cp16(uint32_t dst, const void* src) {
    asm volatile("cp.async.cg.shared.global [%0], [%1], 16;" :: "r"(dst), "l"(src) : "memory");
}
#define CP_COMMIT() asm volatile("cp.async.commit_group;" ::: "memory")
#define CP_WAIT(n)  asm volatile("cp.async.wait_group %0;" :: "n"(n) : "memory")

#define LDSM4(r0,r1,r2,r3,a) \
    asm volatile("ldmatrix.sync.aligned.m8n8.x4.shared.b16 {%0,%1,%2,%3}, [%4];" \
                 : "=r"(r0),"=r"(r1),"=r"(r2),"=r"(r3) : "r"(a))
#define LDSM4T(r0,r1,r2,r3,a) \
    asm volatile("ldmatrix.sync.aligned.m8n8.x4.trans.shared.b16 {%0,%1,%2,%3}, [%4];" \
                 : "=r"(r0),"=r"(r1),"=r"(r2),"=r"(r3) : "r"(a))
#define MMA_BF16(c,a,b0,b1) \
    asm volatile("mma.sync.aligned.m16n8k16.row.col.f32.bf16.bf16.f32 " \
                 "{%0,%1,%2,%3}, {%4,%5,%6,%7}, {%8,%9}, {%0,%1,%2,%3};" \
                 : "+f"((c)[0]),"+f"((c)[1]),"+f"((c)[2]),"+f"((c)[3]) \
                 : "r"((a)[0]),"r"((a)[1]),"r"((a)[2]),"r"((a)[3]),"r"(b0),"r"(b1))

__device__ __forceinline__ void split_bf16(float v, __nv_bfloat16& h, __nv_bfloat16& l) {
    h = __float2bfloat16_rn(v);
    l = __float2bfloat16_rn(v - __bfloat162float(h));
}

// ---------------- graph preprocessing ----------------
__global__ void k_init(int n) {
    int i = blockIdx.x * blockDim.x + threadIdx.x;
    if (i < n) { g_counts[i] = 0; g_cursor[i] = 0; }
}
__global__ void k_count(const int* __restrict__ col, int E) {
    int e = blockIdx.x * blockDim.x + threadIdx.x;
    if (e < E) atomicAdd(&g_counts[col[e]], 1);
}
__global__ void k_scan(int n, int E) {
    __shared__ int sh[1024];
    int tid = threadIdx.x;
    int C = (n + 1023) >> 10;
    int base = tid * C;
    int s = 0;
    for (int i = 0; i < C; i++) { int idx = base + i; if (idx < n) s += g_counts[idx]; }
    sh[tid] = s; __syncthreads();
    for (int off = 1; off < 1024; off <<= 1) {
        int v = (tid >= off) ? sh[tid - off] : 0;
        __syncthreads();
        sh[tid] += v;
        __syncthreads();
    }
    int run = (tid > 0) ? sh[tid - 1] : 0;
    for (int i = 0; i < C; i++) {
        int idx = base + i;
        if (idx < n) {
            g_rowptr[idx] = run;
            int c = g_counts[idx];
            run += c;
            g_dis[idx] = rsqrtf((float)(c + 1));
        }
    }
    if (tid == 0) g_rowptr[n] = E;
}
__global__ void k_scatter(const int* __restrict__ row, const int* __restrict__ col, int E) {
    int e = blockIdx.x * blockDim.x + threadIdx.x;
    if (e < E) {
        int c = col[e];
        int p = g_rowptr[c] + atomicAdd(&g_cursor[c], 1);
        g_csr[p] = row[e];
    }
}

// ---------------- B' prep ----------------
__global__ void k_prep_b(const float* __restrict__ w1, const float* __restrict__ w2) {
    int idx = blockIdx.x * blockDim.x + threadIdx.x;
    if (idx >= NL * 512 * 256) return;
    int n = idx & 255;
    int k = (idx >> 8) & 511;
    int l = idx >> 17;
    float beta = logf(1.0f / (float)(l + 1) + 1.0f);
    float v = (k < 256) ? w1[(l << 16) + (k << 8) + n]
                        : w2[(l << 16) + ((k - 256) << 8) + n];
    float val = 0.5f * beta * v;
    if (k == n || k == n + 256) val += 0.5f * (1.0f - beta);
    __nv_bfloat16 h, lo; split_bf16(val, h, lo);
    g_bhh[idx] = h;
    g_bll[idx] = lo;
}

// ---------------- CSR gather (fp16 input) -> bf16 hi/lo A rows (k 0..255) ----------------
__global__ __launch_bounds__(256) void k_gather(int n) {
    int w = (blockIdx.x * blockDim.x + threadIdx.x) >> 5;
    int lane = threadIdx.x & 31;
    if (w >= n) return;
    const uint4* __restrict__ hn = (const uint4*)g_hn;   // 8 halves per uint4; row = 32 uint4
    float dc = g_dis[w];
    float a[8];
    {
        uint4 v = hn[w * 32 + lane];
        const __half2* ph = (const __half2*)&v;
#pragma unroll
        for (int j = 0; j < 4; j++) {
            float2 f = __half22float2(ph[j]);
            a[2 * j] = dc * f.x; a[2 * j + 1] = dc * f.y;
        }
    }
    int beg = g_rowptr[w], end = g_rowptr[w + 1];
    int i = beg;
    for (; i + 3 < end; i += 4) {
        int s0 = g_csr[i], s1 = g_csr[i + 1], s2 = g_csr[i + 2], s3 = g_csr[i + 3];
        float w0 = g_dis[s0], w1 = g_dis[s1], w2 = g_dis[s2], w3 = g_dis[s3];
        uint4 p = hn[s0 * 32 + lane], q = hn[s1 * 32 + lane];
        uint4 r = hn[s2 * 32 + lane], t = hn[s3 * 32 + lane];
        const __half2* pp = (const __half2*)&p;
        const __half2* qq = (const __half2*)&q;
        const __half2* rr = (const __half2*)&r;
        const __half2* tt = (const __half2*)&t;
#pragma unroll
        for (int j = 0; j < 4; j++) {
            float2 fp = __half22float2(pp[j]);
            float2 fq = __half22float2(qq[j]);
            float2 fr = __half22float2(rr[j]);
            float2 ft = __half22float2(tt[j]);
            a[2 * j]     = fmaf(w0, fp.x, fmaf(w1, fq.x, fmaf(w2, fr.x, fmaf(w3, ft.x, a[2 * j]))));
            a[2 * j + 1] = fmaf(w0, fp.y, fmaf(w1, fq.y, fmaf(w2, fr.y, fmaf(w3, ft.y, a[2 * j + 1]))));
        }
    }
    for (; i < end; i++) {
        int s0 = g_csr[i];
        float w0 = g_dis[s0];
        uint4 p = hn[s0 * 32 + lane];
        const __half2* pp = (const __half2*)&p;
#pragma unroll
        for (int j = 0; j < 4; j++) {
            float2 fp = __half22float2(pp[j]);
            a[2 * j]     = fmaf(w0, fp.x, a[2 * j]);
            a[2 * j + 1] = fmaf(w0, fp.y, a[2 * j + 1]);
        }
    }
    size_t ro = (size_t)w * 512 + lane * 8;
    __nv_bfloat16 hh[8], ll[8];
#pragma unroll
    for (int j = 0; j < 8; j++) {
        float v = a[j] * dc;
        split_bf16(v, hh[j], ll[j]);
    }
    *(uint4*)&g_ahh[ro] = *(uint4*)hh;
    *(uint4*)&g_all[ro] = *(uint4*)ll;
}

// ---------------- bf16 3-pass tensor GEMM, 128m x 256n CTA, K=512 (8x64 chunks) ----------------
#define STAGE 98304u
#define SMTOT 196608
__global__ __launch_bounds__(256, 1) void k_mma(int layer, int nvalid) {
    extern __shared__ char smem[];
    uint32_t sb = s2u(smem);
    const int tid = threadIdx.x, lane = tid & 31, wid = tid >> 5;
    const int T = blockIdx.x;

    const __nv_bfloat16* __restrict__ Agh = g_ahh + (size_t)T * 128 * 512;
    const __nv_bfloat16* __restrict__ Agl = g_all + (size_t)T * 128 * 512;
    const __nv_bfloat16* __restrict__ Bgh = g_bhh + (size_t)layer * 512 * 256;
    const __nv_bfloat16* __restrict__ Bgl = g_bll + (size_t)layer * 512 * 256;

    auto load_chunk = [&](int c, int st) {
        uint32_t s0 = sb + st * STAGE;
#pragma unroll
        for (int i = 0; i < 4; i++) {
            int e = tid + i * 256;
            int m = e >> 3, kc = e & 7;
            uint32_t da = (uint32_t)(m * 128 + ((kc ^ (m & 7)) << 4));
            cp16(s0 + da, Agh + (size_t)m * 512 + c * 64 + kc * 8);
            cp16(s0 + 16384 + da, Agl + (size_t)m * 512 + c * 64 + kc * 8);
        }
#pragma unroll
        for (int i = 0; i < 8; i++) {
            int e = tid + i * 256;
            int k = e >> 5, ncol = e & 31;
            int nhalf = ncol >> 4, nc = ncol & 15;
            uint32_t db = (uint32_t)(nhalf * 16384 + k * 256 + ((nc ^ (k & 7)) << 4));
            size_t src = (size_t)(c * 64 + k) * 256 + nhalf * 128 + nc * 8;
            cp16(s0 + 32768 + db, Bgh + src);
            cp16(s0 + 65536 + db, Bgl + src);
        }
        CP_COMMIT();
    };

    float acc[4][8][4];
#pragma unroll
    for (int i = 0; i < 4; i++)
#pragma unroll
        for (int j = 0; j < 8; j++)
#pragma unroll
            for (int q = 0; q < 4; q++) acc[i][j][q] = 0.f;

    const int wm = (wid & 1) * 64;
    const int wng = (wid >> 1) * 64;
    const uint32_t nhb = (uint32_t)((wng >> 7) * 16384);
    const int ncb = (wng & 127) >> 3;

    auto compute = [&](uint32_t s0) {
        uint32_t sah = s0, sal = s0 + 16384, sbh = s0 + 32768, sbl = s0 + 65536;
#pragma unroll
        for (int kq = 0; kq < 4; kq++) {
            uint32_t ah[4][4], al[4][4], bh[4][4], bl[4][4];
#pragma unroll
            for (int mi = 0; mi < 4; mi++) {
                int m = wm + mi * 16 + (lane & 15);
                int kcc = kq * 2 + (lane >> 4);
                uint32_t ad = (uint32_t)(m * 128 + ((kcc ^ (m & 7)) << 4));
                LDSM4(ah[mi][0], ah[mi][1], ah[mi][2], ah[mi][3], sah + ad);
                LDSM4(al[mi][0], al[mi][1], al[mi][2], al[mi][3], sal + ad);
            }
#pragma unroll
            for (int nj = 0; nj < 4; nj++) {
                int kr = kq * 16 + (lane & 15);
                int nc = ncb + nj * 2 + (lane >> 4);
                uint32_t bd = nhb + (uint32_t)(kr * 256 + ((nc ^ (kr & 7)) << 4));
                LDSM4T(bh[nj][0], bh[nj][1], bh[nj][2], bh[nj][3], sbh + bd);
                LDSM4T(bl[nj][0], bl[nj][1], bl[nj][2], bl[nj][3], sbl + bd);
            }
#pragma unroll
            for (int mi = 0; mi < 4; mi++)
#pragma unroll
                for (int nt = 0; nt < 8; nt++) {
                    int nj = nt >> 1, pq = (nt & 1) * 2;
                    MMA_BF16(acc[mi][nt], ah[mi], bh[nj][pq], bh[nj][pq + 1]);
                    MMA_BF16(acc[mi][nt], ah[mi], bl[nj][pq], bl[nj][pq + 1]);
                    MMA_BF16(acc[mi][nt], al[mi], bh[nj][pq], bh[nj][pq + 1]);
                }
        }
    };

    load_chunk(0, 0);
    for (int ch = 0; ch < 8; ch++) {
        if (ch < 7) { load_chunk(ch + 1, (ch + 1) & 1); CP_WAIT(1); }
        else        { CP_WAIT(0); }
        __syncthreads();
        compute(sb + (ch & 1) * STAGE);
        __syncthreads();
    }

    // ---- epilogue: write g_ha (fp32), LN partials ----
    float s = 0.f, ss = 0.f;
    int rbase = T * 128 + wm + (lane >> 2);
    int cbase = wng + (lane & 3) * 2;
#pragma unroll
    for (int mi = 0; mi < 4; mi++) {
        int r0 = rbase + mi * 16;
        int r1 = r0 + 8;
        bool v0 = r0 < nvalid, v1 = r1 < nvalid;
#pragma unroll
        for (int nt = 0; nt < 8; nt++) {
            int col = cbase + nt * 8;
            if (v0) {
                float2 p = make_float2(acc[mi][nt][0], acc[mi][nt][1]);
                *(float2*)&g_ha[(size_t)r0 * DH + col] = p;
                s += p.x + p.y; ss += p.x * p.x + p.y * p.y;
            }
            if (v1) {
                float2 p = make_float2(acc[mi][nt][2], acc[mi][nt][3]);
                *(float2*)&g_ha[(size_t)r1 * DH + col] = p;
                s += p.x + p.y; ss += p.x * p.x + p.y * p.y;
            }
        }
    }
    __syncthreads();
    float* red = (float*)smem;
    red[tid] = s; red[256 + tid] = ss;
    __syncthreads();
    for (int o = 128; o > 0; o >>= 1) {
        if (tid < o) { red[tid] += red[tid + o]; red[256 + tid] += red[256 + tid + o]; }
        __syncthreads();
    }
    if (tid == 0) { g_part[T] = red[0]; g_part2[T] = red[256]; }
}

// ---------------- layernorm: finalize + normalize+relu, fp32 g_ha -> fp16 g_hn ----------------
__global__ __launch_bounds__(256) void k_norm(const float* __restrict__ gamma,
                                              const float* __restrict__ beta,
                                              int total4, int nparts, float invcnt) {
    __shared__ float sred[512];
    __shared__ float s_scale[256], s_shift[256];
    const int tid = threadIdx.x;

    float s = 0.f, ss = 0.f;
    for (int i = tid; i < nparts; i += 256) { s += g_part[i]; ss += g_part2[i]; }
    sred[tid] = s; sred[256 + tid] = ss;
    __syncthreads();
    for (int o = 128; o > 0; o >>= 1) {
        if (tid < o) { sred[tid] += sred[tid + o]; sred[256 + tid] += sred[256 + tid + o]; }
        __syncthreads();
    }
    float mu = sred[0] * invcnt;
    float var = fmaxf(sred[256] * invcnt - mu * mu, 0.f);
    float inv = 1.0f / (sqrtf(var) + 1e-5f);
    float gch = gamma[tid] * inv;
    s_scale[tid] = gch;
    s_shift[tid] = beta[tid] - mu * gch;
    __syncthreads();

    int stride = gridDim.x * 256;
    for (int i = blockIdx.x * 256 + tid; i < total4; i += stride) {
        float4 v = ((const float4*)g_ha)[i];
        int f = (i * 4) & 255;
        float4 g = *(float4*)&s_scale[f];
        float4 b = *(float4*)&s_shift[f];
        v.x = fmaxf(fmaf(v.x, g.x, b.x), 0.f);
        v.y = fmaxf(fmaf(v.y, g.y, b.y), 0.f);
        v.z = fmaxf(fmaf(v.z, g.z, b.z), 0.f);
        v.w = fmaxf(fmaf(v.w, g.w, b.w), 0.f);
        __half2 h0 = __floats2half2_rn(v.x, v.y);
        __half2 h1 = __floats2half2_rn(v.z, v.w);
        __half2* dst = (__half2*)&g_hn[(size_t)i * 4];
        dst[0] = h0;
        dst[1] = h1;
    }
}

// ---------------- dense f32x2 GEMM for lin1 / lin2 ----------------
// MODE 0: x0 = relu(x @ lin1_w + b) -> g_hn (fp16) + g_ahh/g_all (k 256..511)
// MODE 2: out = relu(norm7(g_ha) @ lin2_w + b) -> Cext
template <int MODE>
__global__ __launch_bounds__(256, 2)
void k_gemm(const float* __restrict__ Aext, const float* __restrict__ Bext,
            const float* __restrict__ bias, float* __restrict__ Cext,
            int M, int K, int ldb,
            const float* __restrict__ ngamma, const float* __restrict__ nbeta,
            int nparts, float invcnt)
{
    __shared__ float As[16][128];
    __shared__ float Bs[16][128];
    __shared__ float s_scale[256], s_shift[256];
    int tid = threadIdx.x;

    if (MODE == 2) {
        float* red = &As[0][0];
        float s = 0.f, ss = 0.f;
        for (int i = tid; i < nparts; i += 256) { s += g_part[i]; ss += g_part2[i]; }
        red[tid] = s; red[256 + tid] = ss;
        __syncthreads();
        for (int o = 128; o > 0; o >>= 1) {
            if (tid < o) { red[tid] += red[tid + o]; red[256 + tid] += red[256 + tid + o]; }
            __syncthreads();
        }
        float m = red[0] * invcnt;
        float var = fmaxf(red[256] * invcnt - m * m, 0.f);
        float inv = 1.0f / (sqrtf(var) + 1e-5f);
        float gch = ngamma[tid] * inv;
        s_scale[tid] = gch;
        s_shift[tid] = nbeta[tid] - m * gch;
        __syncthreads();
    }

    int m0 = blockIdx.x * 128, n0 = blockIdx.y * 128;
    int ty = tid >> 4, tx = tid & 15;

    int ar = tid >> 1;
    int akq = (tid & 1) * 8;
    int am = m0 + ar; if (am > M - 1) am = M - 1;
    int bk = tid >> 4;
    int bnq = (tid & 15) * 8;

    unsigned long long acc[8][4];
#pragma unroll
    for (int i = 0; i < 8; i++)
#pragma unroll
        for (int j = 0; j < 4; j++) acc[i][j] = 0ull;

    for (int k0 = 0; k0 < K; k0 += 16) {
        const float* asrc;
        if (MODE == 0) asrc = Aext + am * 128 + k0 + akq;
        else           asrc = &g_ha[(size_t)am * DH + k0 + akq];
        float4 av0 = *(const float4*)asrc;
        float4 av1 = *(const float4*)(asrc + 4);
        if (MODE == 2) {
            float4 c0 = *(float4*)&s_scale[k0 + akq];
            float4 c1 = *(float4*)&s_scale[k0 + akq + 4];
            float4 d0 = *(float4*)&s_shift[k0 + akq];
            float4 d1 = *(float4*)&s_shift[k0 + akq + 4];
            av0.x = fmaxf(fmaf(av0.x, c0.x, d0.x), 0.f);
            av0.y = fmaxf(fmaf(av0.y, c0.y, d0.y), 0.f);
            av0.z = fmaxf(fmaf(av0.z, c0.z, d0.z), 0.f);
            av0.w = fmaxf(fmaf(av0.w, c0.w, d0.w), 0.f);
            av1.x = fmaxf(fmaf(av1.x, c1.x, d1.x), 0.f);
            av1.y = fmaxf(fmaf(av1.y, c1.y, d1.y), 0.f);
            av1.z = fmaxf(fmaf(av1.z, c1.z, d1.z), 0.f);
            av1.w = fmaxf(fmaf(av1.w, c1.w, d1.w), 0.f);
        }
        const float* bsrc = Bext + (k0 + bk) * ldb + n0 + bnq;
        float4 bv0 = *(const float4*)bsrc;
        float4 bv1 = *(const float4*)(bsrc + 4);

        __syncthreads();
        As[akq + 0][ar] = av0.x; As[akq + 1][ar] = av0.y;
        As[akq + 2][ar] = av0.z; As[akq + 3][ar] = av0.w;
        As[akq + 4][ar] = av1.x; As[akq + 5][ar] = av1.y;
        As[akq + 6][ar] = av1.z; As[akq + 7][ar] = av1.w;
        *(float4*)&Bs[bk][bnq] = bv0;
        *(float4*)&Bs[bk][bnq + 4] = bv1;
        __syncthreads();

#pragma unroll
        for (int kk = 0; kk < 16; kk++) {
            float4 aA = *(const float4*)&As[kk][ty * 8];
            float4 aB = *(const float4*)&As[kk][ty * 8 + 4];
            ulonglong2 bb0 = *(const ulonglong2*)&Bs[kk][tx * 4];
            ulonglong2 bb1 = *(const ulonglong2*)&Bs[kk][64 + tx * 4];
            unsigned long long ad[8];
            ad[0] = pack_dup(aA.x); ad[1] = pack_dup(aA.y);
            ad[2] = pack_dup(aA.z); ad[3] = pack_dup(aA.w);
            ad[4] = pack_dup(aB.x); ad[5] = pack_dup(aB.y);
            ad[6] = pack_dup(aB.z); ad[7] = pack_dup(aB.w);
#pragma unroll
            for (int i = 0; i < 8; i++) {
                FMA2(acc[i][0], ad[i], bb0.x);
                FMA2(acc[i][1], ad[i], bb0.y);
                FMA2(acc[i][2], ad[i], bb1.x);
                FMA2(acc[i][3], ad[i], bb1.y);
            }
        }
    }

    int nA = n0 + tx * 4;
    int nB = n0 + 64 + tx * 4;
    float4 biasA = *(const float4*)&bias[nA];
    float4 biasB = *(const float4*)&bias[nB];

#pragma unroll
    for (int i = 0; i < 8; i++) {
        int m = m0 + ty * 8 + i;
        if (m >= M) continue;
        float2 p0 = unpack2(acc[i][0]), p1 = unpack2(acc[i][1]);
        float2 p2 = unpack2(acc[i][2]), p3 = unpack2(acc[i][3]);
        float4 vA = make_float4(fmaxf(p0.x + biasA.x, 0.f), fmaxf(p0.y + biasA.y, 0.f),
                                fmaxf(p1.x + biasA.z, 0.f), fmaxf(p1.y + biasA.w, 0.f));
        float4 vB = make_float4(fmaxf(p2.x + biasB.x, 0.f), fmaxf(p2.y + biasB.y, 0.f),
                                fmaxf(p3.x + biasB.z, 0.f), fmaxf(p3.y + biasB.w, 0.f));

        if (MODE == 0) {
            size_t o = (size_t)m * DH;
            __half2* dA = (__half2*)&g_hn[o + nA];
            dA[0] = __floats2half2_rn(vA.x, vA.y);
            dA[1] = __floats2half2_rn(vA.z, vA.w);
            __half2* dB = (__half2*)&g_hn[o + nB];
            dB[0] = __floats2half2_rn(vB.x, vB.y);
            dB[1] = __floats2half2_rn(vB.z, vB.w);
            size_t ro = (size_t)m * 512 + 256;
            __nv_bfloat16 h_[4], l_[4];
            split_bf16(vA.x, h_[0], l_[0]); split_bf16(vA.y, h_[1], l_[1]);
            split_bf16(vA.z, h_[2], l_[2]); split_bf16(vA.w, h_[3], l_[3]);
            *(uint2*)&g_ahh[ro + nA] = *(uint2*)h_;
            *(uint2*)&g_all[ro + nA] = *(uint2*)l_;
            split_bf16(vB.x, h_[0], l_[0]); split_bf16(vB.y, h_[1], l_[1]);
            split_bf16(vB.z, h_[2], l_[2]); split_bf16(vB.w, h_[3], l_[3]);
            *(uint2*)&g_ahh[ro + nB] = *(uint2*)h_;
            *(uint2*)&g_all[ro + nB] = *(uint2*)l_;
        } else {
            size_t o = (size_t)m * 128;
            *(float4*)&Cext[o + nA] = vA;
            *(float4*)&Cext[o + nB] = vB;
        }
    }
}

// ---------------- launch (single stream) ----------------
extern "C" void kernel_launch(void* const* d_in, const int* in_sizes, int n_in,
                              void* d_out, int out_size) {
    const float* x      = (const float*)d_in[0];
    const int*   ei     = (const int*)d_in[1];
    const float* lin1_w = (const float*)d_in[2];
    const float* lin1_b = (const float*)d_in[3];
    const float* w1     = (const float*)d_in[4];
    const float* w2     = (const float*)d_in[5];
    const float* gamma  = (const float*)d_in[6];
    const float* betab  = (const float*)d_in[7];
    const float* lin2_w = (const float*)d_in[8];
    const float* lin2_b = (const float*)d_in[9];
    float* out = (float*)d_out;

    int N = in_sizes[0] / 128;
    int E = in_sizes[1] / 2;
    const int* row = ei;
    const int* col = ei + E;

    int Mt = (N + 127) / 128;
    int total4 = N * (DH / 4);
    float invcnt = 1.0f / ((float)N * (float)DH);

    static int smem_set = 0;
    if (!smem_set) {
        cudaFuncSetAttribute(k_mma, cudaFuncAttributeMaxDynamicSharedMemorySize, SMTOT);
        smem_set = 1;
    }

    k_init<<<(N + 255) / 256, 256>>>(N);
    k_count<<<(E + 255) / 256, 256>>>(col, E);
    k_scan<<<1, 1024>>>(N, E);
    k_scatter<<<(E + 255) / 256, 256>>>(row, col, E);
    k_prep_b<<<(NL * 512 * 256 + 255) / 256, 256>>>(w1, w2);

    // x0 = relu(x @ lin1_w + b) -> g_hn (fp16) + g_ahh/g_all upper-k
    k_gemm<0><<<dim3(Mt, 2), 256>>>(x, lin1_w, lin1_b, nullptr, N, 128, 256,
                                    nullptr, nullptr, 0, 0.f);

    for (int l = 0; l < NL; l++) {
        k_gather<<<(N * 32 + 255) / 256, 256>>>(N);
        k_mma<<<Mt, 256, SMTOT>>>(l, N);
        if (l < NL - 1)
            k_norm<<<1184, 256>>>(gamma + l * DH, betab + l * DH, total4, Mt, invcnt);
    }

    // out = relu(norm7(g_ha) @ lin2_w + b)
    k_gemm<2><<<dim3(Mt, 1), 256>>>(nullptr, lin2_w, lin2_b, out, N, 256, 128,
                                    gamma + 7 * DH, betab + 7 * DH, Mt, invcnt);
}

// round 11
// speedup vs baseline: 1.8015x; 1.1914x over previous
#include <cuda_runtime.h>
#include <cuda_bf16.h>
#include <cuda_fp16.h>
#include <math.h>
#include <stdint.h>

#define NN 50000
#define EE 800000
#define DH 256
#define NL 8
#define NTILES ((NN + 127) / 128)
#define NPAD (NTILES * 128)

// ---------------- scratch ----------------
__device__ float g_ha[NN * DH];                                 // fp32 h_out (per-layer)
__device__ __align__(16) __half g_hn[(size_t)NN * DH];          // fp16 gather operand: relu(norm(h)) / x0
__device__ __align__(16) __half g_a[(size_t)NPAD * 512];        // fp16 A [node][k] k<256 agg, k>=256 x0
__device__ __align__(16) __half g_bh[(size_t)NL * 512 * 256];   // B' hi (fp16)
__device__ __align__(16) __half g_bl[(size_t)NL * 512 * 256];   // B' lo (fp16)
__device__ float g_dis[NN];
__device__ int   g_counts[NN];
__device__ int   g_cursor[NN];
__device__ int   g_rowptr[NN + 1];
__device__ int   g_csr[EE];
__device__ float g_part[NTILES + 8];
__device__ float g_part2[NTILES + 8];

// ---------------- helpers ----------------
__device__ __forceinline__ uint32_t s2u(const void* p) {
    uint32_t a;
    asm("{ .reg .u64 t; cvta.to.shared.u64 t, %1; cvt.u32.u64 %0, t; }" : "=r"(a) : "l"(p));
    return a;
}
__device__ __forceinline__ unsigned long long pack_dup(float x) {
    unsigned long long r; unsigned u = __float_as_uint(x);
    asm("mov.b64 %0, {%1, %1};" : "=l"(r) : "r"(u));
    return r;
}
__device__ __forceinline__ float2 unpack2(unsigned long long v) {
    unsigned lo, hi;
    asm("mov.b64 {%0, %1}, %2;" : "=r"(lo), "=r"(hi) : "l"(v));
    return make_float2(__uint_as_float(lo), __uint_as_float(hi));
}
#define FMA2(acc, a, b) asm("fma.rn.f32x2 %0, %1, %2, %0;" : "+l"(acc) : "l"(a), "l"(b))

__device__ __forceinline__ void cp16(uint32_t dst, const void* src) {
    asm volatile("cp.async.cg.shared.global [%0], [%1], 16;" :: "r"(dst), "l"(src) : "memory");
}
#define CP_COMMIT() asm volatile("cp.async.commit_group;" ::: "memory")
#define CP_WAIT(n)  asm volatile("cp.async.wait_group %0;" :: "n"(n) : "memory")

#define LDSM4(r0,r1,r2,r3,a) \
    asm volatile("ldmatrix.sync.aligned.m8n8.x4.shared.b16 {%0,%1,%2,%3}, [%4];" \
                 : "=r"(r0),"=r"(r1),"=r"(r2),"=r"(r3) : "r"(a))
#define LDSM4T(r0,r1,r2,r3,a) \
    asm volatile("ldmatrix.sync.aligned.m8n8.x4.trans.shared.b16 {%0,%1,%2,%3}, [%4];" \
                 : "=r"(r0),"=r"(r1),"=r"(r2),"=r"(r3) : "r"(a))
#define MMA_F16(c,a,b0,b1) \
    asm volatile("mma.sync.aligned.m16n8k16.row.col.f32.f16.f16.f32 " \
                 "{%0,%1,%2,%3}, {%4,%5,%6,%7}, {%8,%9}, {%0,%1,%2,%3};" \
                 : "+f"((c)[0]),"+f"((c)[1]),"+f"((c)[2]),"+f"((c)[3]) \
                 : "r"((a)[0]),"r"((a)[1]),"r"((a)[2]),"r"((a)[3]),"r"(b0),"r"(b1))

// ---------------- graph preprocessing ----------------
__global__ void k_init(int n) {
    int i = blockIdx.x * blockDim.x + threadIdx.x;
    if (i < n) { g_counts[i] = 0; g_cursor[i] = 0; }
}
__global__ void k_count(const int* __restrict__ col, int E) {
    int e = blockIdx.x * blockDim.x + threadIdx.x;
    if (e < E) atomicAdd(&g_counts[col[e]], 1);
}
__global__ void k_scan(int n, int E) {
    __shared__ int sh[1024];
    int tid = threadIdx.x;
    int C = (n + 1023) >> 10;
    int base = tid * C;
    int s = 0;
    for (int i = 0; i < C; i++) { int idx = base + i; if (idx < n) s += g_counts[idx]; }
    sh[tid] = s; __syncthreads();
    for (int off = 1; off < 1024; off <<= 1) {
        int v = (tid >= off) ? sh[tid - off] : 0;
        __syncthreads();
        sh[tid] += v;
        __syncthreads();
    }
    int run = (tid > 0) ? sh[tid - 1] : 0;
    for (int i = 0; i < C; i++) {
        int idx = base + i;
        if (idx < n) {
            g_rowptr[idx] = run;
            int c = g_counts[idx];
            run += c;
            g_dis[idx] = rsqrtf((float)(c + 1));
        }
    }
    if (tid == 0) g_rowptr[n] = E;
}
__global__ void k_scatter(const int* __restrict__ row, const int* __restrict__ col, int E) {
    int e = blockIdx.x * blockDim.x + threadIdx.x;
    if (e < E) {
        int c = col[e];
        int p = g_rowptr[c] + atomicAdd(&g_cursor[c], 1);
        g_csr[p] = row[e];
    }
}

// ---------------- B' prep: fp16 hi/lo split ----------------
__global__ void k_prep_b(const float* __restrict__ w1, const float* __restrict__ w2) {
    int idx = blockIdx.x * blockDim.x + threadIdx.x;
    if (idx >= NL * 512 * 256) return;
    int n = idx & 255;
    int k = (idx >> 8) & 511;
    int l = idx >> 17;
    float beta = logf(1.0f / (float)(l + 1) + 1.0f);
    float v = (k < 256) ? w1[(l << 16) + (k << 8) + n]
                        : w2[(l << 16) + ((k - 256) << 8) + n];
    float val = 0.5f * beta * v;
    if (k == n || k == n + 256) val += 0.5f * (1.0f - beta);
    __half h = __float2half_rn(val);
    __half lo = __float2half_rn(val - __half2float(h));
    g_bh[idx] = h;
    g_bl[idx] = lo;
}

// ---------------- CSR gather (fp16 in) -> fp16 A rows (k 0..255) ----------------
__global__ __launch_bounds__(256) void k_gather(int n) {
    int w = (blockIdx.x * blockDim.x + threadIdx.x) >> 5;
    int lane = threadIdx.x & 31;
    if (w >= n) return;
    const uint4* __restrict__ hn = (const uint4*)g_hn;   // 8 halves per uint4; row = 32 uint4
    float dc = g_dis[w];
    float a[8];
    {
        uint4 v = hn[w * 32 + lane];
        const __half2* ph = (const __half2*)&v;
#pragma unroll
        for (int j = 0; j < 4; j++) {
            float2 f = __half22float2(ph[j]);
            a[2 * j] = dc * f.x; a[2 * j + 1] = dc * f.y;
        }
    }
    int beg = g_rowptr[w], end = g_rowptr[w + 1];
    int i = beg;
    for (; i + 3 < end; i += 4) {
        int s0 = g_csr[i], s1 = g_csr[i + 1], s2 = g_csr[i + 2], s3 = g_csr[i + 3];
        float w0 = g_dis[s0], w1 = g_dis[s1], w2 = g_dis[s2], w3 = g_dis[s3];
        uint4 p = hn[s0 * 32 + lane], q = hn[s1 * 32 + lane];
        uint4 r = hn[s2 * 32 + lane], t = hn[s3 * 32 + lane];
        const __half2* pp = (const __half2*)&p;
        const __half2* qq = (const __half2*)&q;
        const __half2* rr = (const __half2*)&r;
        const __half2* tt = (const __half2*)&t;
#pragma unroll
        for (int j = 0; j < 4; j++) {
            float2 fp = __half22float2(pp[j]);
            float2 fq = __half22float2(qq[j]);
            float2 fr = __half22float2(rr[j]);
            float2 ft = __half22float2(tt[j]);
            a[2 * j]     = fmaf(w0, fp.x, fmaf(w1, fq.x, fmaf(w2, fr.x, fmaf(w3, ft.x, a[2 * j]))));
            a[2 * j + 1] = fmaf(w0, fp.y, fmaf(w1, fq.y, fmaf(w2, fr.y, fmaf(w3, ft.y, a[2 * j + 1]))));
        }
    }
    for (; i < end; i++) {
        int s0 = g_csr[i];
        float w0 = g_dis[s0];
        uint4 p = hn[s0 * 32 + lane];
        const __half2* pp = (const __half2*)&p;
#pragma unroll
        for (int j = 0; j < 4; j++) {
            float2 fp = __half22float2(pp[j]);
            a[2 * j]     = fmaf(w0, fp.x, a[2 * j]);
            a[2 * j + 1] = fmaf(w0, fp.y, a[2 * j + 1]);
        }
    }
    size_t ro = (size_t)w * 512 + lane * 8;
    __half hh[8];
#pragma unroll
    for (int j = 0; j < 8; j++) hh[j] = __float2half_rn(a[j] * dc);
    *(uint4*)&g_a[ro] = *(uint4*)hh;
}

// ---------------- fp16 2-pass tensor GEMM, 128m x 256n CTA, K=512 (8x64 chunks) ----------------
// stage = A(16K) + Bh(32K) + Bl(32K) = 80KB, x2 = 160KB
#define STAGE 81920u
#define SMTOT 163840
__global__ __launch_bounds__(256, 1) void k_mma(int layer, int nvalid) {
    extern __shared__ char smem[];
    uint32_t sb = s2u(smem);
    const int tid = threadIdx.x, lane = tid & 31, wid = tid >> 5;
    const int T = blockIdx.x;

    const __half* __restrict__ Ag = g_a + (size_t)T * 128 * 512;
    const __half* __restrict__ Bgh = g_bh + (size_t)layer * 512 * 256;
    const __half* __restrict__ Bgl = g_bl + (size_t)layer * 512 * 256;

    auto load_chunk = [&](int c, int st) {
        uint32_t s0 = sb + st * STAGE;
#pragma unroll
        for (int i = 0; i < 4; i++) {
            int e = tid + i * 256;
            int m = e >> 3, kc = e & 7;
            uint32_t da = (uint32_t)(m * 128 + ((kc ^ (m & 7)) << 4));
            cp16(s0 + da, Ag + (size_t)m * 512 + c * 64 + kc * 8);
        }
#pragma unroll
        for (int i = 0; i < 8; i++) {
            int e = tid + i * 256;
            int k = e >> 5, ncol = e & 31;
            int nhalf = ncol >> 4, nc = ncol & 15;
            uint32_t db = (uint32_t)(nhalf * 16384 + k * 256 + ((nc ^ (k & 7)) << 4));
            size_t src = (size_t)(c * 64 + k) * 256 + nhalf * 128 + nc * 8;
            cp16(s0 + 16384 + db, Bgh + src);
            cp16(s0 + 49152 + db, Bgl + src);
        }
        CP_COMMIT();
    };

    float acc[4][8][4];
#pragma unroll
    for (int i = 0; i < 4; i++)
#pragma unroll
        for (int j = 0; j < 8; j++)
#pragma unroll
            for (int q = 0; q < 4; q++) acc[i][j][q] = 0.f;

    const int wm = (wid & 1) * 64;
    const int wng = (wid >> 1) * 64;
    const uint32_t nhb = (uint32_t)((wng >> 7) * 16384);
    const int ncb = (wng & 127) >> 3;

    auto compute = [&](uint32_t s0) {
        uint32_t sa = s0, sbh = s0 + 16384, sbl = s0 + 49152;
#pragma unroll
        for (int kq = 0; kq < 4; kq++) {
            uint32_t ar[4][4], bh[4][4], bl[4][4];
#pragma unroll
            for (int mi = 0; mi < 4; mi++) {
                int m = wm + mi * 16 + (lane & 15);
                int kcc = kq * 2 + (lane >> 4);
                uint32_t ad = (uint32_t)(m * 128 + ((kcc ^ (m & 7)) << 4));
                LDSM4(ar[mi][0], ar[mi][1], ar[mi][2], ar[mi][3], sa + ad);
            }
#pragma unroll
            for (int nj = 0; nj < 4; nj++) {
                int kr = kq * 16 + (lane & 15);
                int nc = ncb + nj * 2 + (lane >> 4);
                uint32_t bd = nhb + (uint32_t)(kr * 256 + ((nc ^ (kr & 7)) << 4));
                LDSM4T(bh[nj][0], bh[nj][1], bh[nj][2], bh[nj][3], sbh + bd);
                LDSM4T(bl[nj][0], bl[nj][1], bl[nj][2], bl[nj][3], sbl + bd);
            }
#pragma unroll
            for (int mi = 0; mi < 4; mi++)
#pragma unroll
                for (int nt = 0; nt < 8; nt++) {
                    int nj = nt >> 1, pq = (nt & 1) * 2;
                    MMA_F16(acc[mi][nt], ar[mi], bh[nj][pq], bh[nj][pq + 1]);
                    MMA_F16(acc[mi][nt], ar[mi], bl[nj][pq], bl[nj][pq + 1]);
                }
        }
    };

    load_chunk(0, 0);
    for (int ch = 0; ch < 8; ch++) {
        if (ch < 7) { load_chunk(ch + 1, (ch + 1) & 1); CP_WAIT(1); }
        else        { CP_WAIT(0); }
        __syncthreads();
        compute(sb + (ch & 1) * STAGE);
        __syncthreads();
    }

    // ---- epilogue: write g_ha (fp32), LN partials ----
    float s = 0.f, ss = 0.f;
    int rbase = T * 128 + wm + (lane >> 2);
    int cbase = wng + (lane & 3) * 2;
#pragma unroll
    for (int mi = 0; mi < 4; mi++) {
        int r0 = rbase + mi * 16;
        int r1 = r0 + 8;
        bool v0 = r0 < nvalid, v1 = r1 < nvalid;
#pragma unroll
        for (int nt = 0; nt < 8; nt++) {
            int col = cbase + nt * 8;
            if (v0) {
                float2 p = make_float2(acc[mi][nt][0], acc[mi][nt][1]);
                *(float2*)&g_ha[(size_t)r0 * DH + col] = p;
                s += p.x + p.y; ss += p.x * p.x + p.y * p.y;
            }
            if (v1) {
                float2 p = make_float2(acc[mi][nt][2], acc[mi][nt][3]);
                *(float2*)&g_ha[(size_t)r1 * DH + col] = p;
                s += p.x + p.y; ss += p.x * p.x + p.y * p.y;
            }
        }
    }
    __syncthreads();
    float* red = (float*)smem;
    red[tid] = s; red[256 + tid] = ss;
    __syncthreads();
    for (int o = 128; o > 0; o >>= 1) {
        if (tid < o) { red[tid] += red[tid + o]; red[256 + tid] += red[256 + tid + o]; }
        __syncthreads();
    }
    if (tid == 0) { g_part[T] = red[0]; g_part2[T] = red[256]; }
}

// ---------------- layernorm: finalize + normalize+relu, fp32 g_ha -> fp16 g_hn ----------------
__global__ __launch_bounds__(256) void k_norm(const float* __restrict__ gamma,
                                              const float* __restrict__ beta,
                                              int total4, int nparts, float invcnt) {
    __shared__ float sred[512];
    __shared__ float s_scale[256], s_shift[256];
    const int tid = threadIdx.x;

    float s = 0.f, ss = 0.f;
    for (int i = tid; i < nparts; i += 256) { s += g_part[i]; ss += g_part2[i]; }
    sred[tid] = s; sred[256 + tid] = ss;
    __syncthreads();
    for (int o = 128; o > 0; o >>= 1) {
        if (tid < o) { sred[tid] += sred[tid + o]; sred[256 + tid] += sred[256 + tid + o]; }
        __syncthreads();
    }
    float mu = sred[0] * invcnt;
    float var = fmaxf(sred[256] * invcnt - mu * mu, 0.f);
    float inv = 1.0f / (sqrtf(var) + 1e-5f);
    float gch = gamma[tid] * inv;
    s_scale[tid] = gch;
    s_shift[tid] = beta[tid] - mu * gch;
    __syncthreads();

    int stride = gridDim.x * 256;
    for (int i = blockIdx.x * 256 + tid; i < total4; i += stride) {
        float4 v = ((const float4*)g_ha)[i];
        int f = (i * 4) & 255;
        float4 g = *(float4*)&s_scale[f];
        float4 b = *(float4*)&s_shift[f];
        v.x = fmaxf(fmaf(v.x, g.x, b.x), 0.f);
        v.y = fmaxf(fmaf(v.y, g.y, b.y), 0.f);
        v.z = fmaxf(fmaf(v.z, g.z, b.z), 0.f);
        v.w = fmaxf(fmaf(v.w, g.w, b.w), 0.f);
        __half2* dst = (__half2*)&g_hn[(size_t)i * 4];
        dst[0] = __floats2half2_rn(v.x, v.y);
        dst[1] = __floats2half2_rn(v.z, v.w);
    }
}

// ---------------- dense f32x2 GEMM for lin1 / lin2 ----------------
// MODE 0: x0 = relu(x @ lin1_w + b) -> g_hn (fp16) + g_a (fp16, k 256..511)
// MODE 2: out = relu(norm7(g_ha) @ lin2_w + b) -> Cext
__device__ __forceinline__ void nop_marker() {}
template <int MODE>
__global__ __launch_bounds__(256, 2)
void k_gemm(const float* __restrict__ Aext, const float* __restrict__ Bext,
            const float* __restrict__ bias, float* __restrict__ Cext,
            int M, int K, int ldb,
            const float* __restrict__ ngamma, const float* __restrict__ nbeta,
            int nparts, float invcnt)
{
    __shared__ float As[16][128];
    __shared__ float Bs[16][128];
    __shared__ float s_scale[256], s_shift[256];
    int tid = threadIdx.x;

    if (MODE == 2) {
        float* red = &As[0][0];
        float s = 0.f, ss = 0.f;
        for (int i = tid; i < nparts; i += 256) { s += g_part[i]; ss += g_part2[i]; }
        red[tid] = s; red[256 + tid] = ss;
        __syncthreads();
        for (int o = 128; o > 0; o >>= 1) {
            if (tid < o) { red[tid] += red[tid + o]; red[256 + tid] += red[256 + tid + o]; }
            __syncthreads();
        }
        float m = red[0] * invcnt;
        float var = fmaxf(red[256] * invcnt - m * m, 0.f);
        float inv = 1.0f / (sqrtf(var) + 1e-5f);
        float gch = ngamma[tid] * inv;
        s_scale[tid] = gch;
        s_shift[tid] = nbeta[tid] - m * gch;
        __syncthreads();
    }

    int m0 = blockIdx.x * 128, n0 = blockIdx.y * 128;
    int ty = tid >> 4, tx = tid & 15;

    int ar = tid >> 1;
    int akq = (tid & 1) * 8;
    int am = m0 + ar; if (am > M - 1) am = M - 1;
    int bk = tid >> 4;
    int bnq = (tid & 15) * 8;

    unsigned long long acc[8][4];
#pragma unroll
    for (int i = 0; i < 8; i++)
#pragma unroll
        for (int j = 0; j < 4; j++) acc[i][j] = 0ull;

    for (int k0 = 0; k0 < K; k0 += 16) {
        const float* asrc;
        if (MODE == 0) asrc = Aext + am * 128 + k0 + akq;
        else           asrc = &g_ha[(size_t)am * DH + k0 + akq];
        float4 av0 = *(const float4*)asrc;
        float4 av1 = *(const float4*)(asrc + 4);
        if (MODE == 2) {
            float4 c0 = *(float4*)&s_scale[k0 + akq];
            float4 c1 = *(float4*)&s_scale[k0 + akq + 4];
            float4 d0 = *(float4*)&s_shift[k0 + akq];
            float4 d1 = *(float4*)&s_shift[k0 + akq + 4];
            av0.x = fmaxf(fmaf(av0.x, c0.x, d0.x), 0.f);
            av0.y = fmaxf(fmaf(av0.y, c0.y, d0.y), 0.f);
            av0.z = fmaxf(fmaf(av0.z, c0.z, d0.z), 0.f);
            av0.w = fmaxf(fmaf(av0.w, c0.w, d0.w), 0.f);
            av1.x = fmaxf(fmaf(av1.x, c1.x, d1.x), 0.f);
            av1.y = fmaxf(fmaf(av1.y, c1.y, d1.y), 0.f);
            av1.z = fmaxf(fmaf(av1.z, c1.z, d1.z), 0.f);
            av1.w = fmaxf(fmaf(av1.w, c1.w, d1.w), 0.f);
        }
        const float* bsrc = Bext + (k0 + bk) * ldb + n0 + bnq;
        float4 bv0 = *(const float4*)bsrc;
        float4 bv1 = *(const float4*)(bsrc + 4);

        __syncthreads();
        As[akq + 0][ar] = av0.x; As[akq + 1][ar] = av0.y;
        As[akq + 2][ar] = av0.z; As[akq + 3][ar] = av0.w;
        As[akq + 4][ar] = av1.x; As[akq + 5][ar] = av1.y;
        As[akq + 6][ar] = av1.z; As[akq + 7][ar] = av1.w;
        *(float4*)&Bs[bk][bnq] = bv0;
        *(float4*)&Bs[bk][bnq + 4] = bv1;
        __syncthreads();

#pragma unroll
        for (int kk = 0; kk < 16; kk++) {
            float4 aA = *(const float4*)&As[kk][ty * 8];
            float4 aB = *(const float4*)&As[kk][ty * 8 + 4];
            ulonglong2 bb0 = *(const ulonglong2*)&Bs[kk][tx * 4];
            ulonglong2 bb1 = *(const ulonglong2*)&Bs[kk][64 + tx * 4];
            unsigned long long ad[8];
            ad[0] = pack_dup(aA.x); ad[1] = pack_dup(aA.y);
            ad[2] = pack_dup(aA.z); ad[3] = pack_dup(aA.w);
            ad[4] = pack_dup(aB.x); ad[5] = pack_dup(aB.y);
            ad[6] = pack_dup(aB.z); ad[7] = pack_dup(aB.w);
#pragma unroll
            for (int i = 0; i < 8; i++) {
                FMA2(acc[i][0], ad[i], bb0.x);
                FMA2(acc[i][1], ad[i], bb0.y);
                FMA2(acc[i][2], ad[i], bb1.x);
                FMA2(acc[i][3], ad[i], bb1.y);
            }
        }
    }

    int nA = n0 + tx * 4;
    int nB = n0 + 64 + tx * 4;
    float4 biasA = *(const float4*)&bias[nA];
    float4 biasB = *(const float4*)&bias[nB];

#pragma unroll
    for (int i = 0; i < 8; i++) {
        int m = m0 + ty * 8 + i;
        if (m >= M) continue;
        float2 p0 = unpack2(acc[i][0]), p1 = unpack2(acc[i][1]);
        float2 p2 = unpack2(acc[i][2]), p3 = unpack2(acc[i][3]);
        float4 vA = make_float4(fmaxf(p0.x + biasA.x, 0.f), fmaxf(p0.y + biasA.y, 0.f),
                                fmaxf(p1.x + biasA.z, 0.f), fmaxf(p1.y + biasA.w, 0.f));
        float4 vB = make_float4(fmaxf(p2.x + biasB.x, 0.f), fmaxf(p2.y + biasB.y, 0.f),
                                fmaxf(p3.x + biasB.z, 0.f), fmaxf(p3.y + biasB.w, 0.f));

        if (MODE == 0) {
            size_t o = (size_t)m * DH;
            __half2* dA = (__half2*)&g_hn[o + nA];
            dA[0] = __floats2half2_rn(vA.x, vA.y);
            dA[1] = __floats2half2_rn(vA.z, vA.w);
            __half2* dB = (__half2*)&g_hn[o + nB];
            dB[0] = __floats2half2_rn(vB.x, vB.y);
            dB[1] = __floats2half2_rn(vB.z, vB.w);
            size_t ro = (size_t)m * 512 + 256;
            __half2* xA = (__half2*)&g_a[ro + nA];
            xA[0] = __floats2half2_rn(vA.x, vA.y);
            xA[1] = __floats2half2_rn(vA.z, vA.w);
            __half2* xB = (__half2*)&g_a[ro + nB];
            xB[0] = __floats2half2_rn(vB.x, vB.y);
            xB[1] = __floats2half2_rn(vB.z, vB.w);
        } else {
            size_t o = (size_t)m * 128;
            *(float4*)&Cext[o + nA] = vA;
            *(float4*)&Cext[o + nB] = vB;
        }
    }
}

// ---------------- launch (single stream) ----------------
extern "C" void kernel_launch(void* const* d_in, const int* in_sizes, int n_in,
                              void* d_out, int out_size) {
    const float* x      = (const float*)d_in[0];
    const int*   ei     = (const int*)d_in[1];
    const float* lin1_w = (const float*)d_in[2];
    const float* lin1_b = (const float*)d_in[3];
    const float* w1     = (const float*)d_in[4];
    const float* w2     = (const float*)d_in[5];
    const float* gamma  = (const float*)d_in[6];
    const float* betab  = (const float*)d_in[7];
    const float* lin2_w = (const float*)d_in[8];
    const float* lin2_b = (const float*)d_in[9];
    float* out = (float*)d_out;

    int N = in_sizes[0] / 128;
    int E = in_sizes[1] / 2;
    const int* row = ei;
    const int* col = ei + E;

    int Mt = (N + 127) / 128;
    int total4 = N * (DH / 4);
    float invcnt = 1.0f / ((float)N * (float)DH);

    static int smem_set = 0;
    if (!smem_set) {
        cudaFuncSetAttribute(k_mma, cudaFuncAttributeMaxDynamicSharedMemorySize, SMTOT);
        smem_set = 1;
    }

    k_init<<<(N + 255) / 256, 256>>>(N);
    k_count<<<(E + 255) / 256, 256>>>(col, E);
    k_scan<<<1, 1024>>>(N, E);
    k_scatter<<<(E + 255) / 256, 256>>>(row, col, E);
    k_prep_b<<<(NL * 512 * 256 + 255) / 256, 256>>>(w1, w2);

    // x0 = relu(x @ lin1_w + b) -> g_hn (fp16) + g_a upper-k (fp16)
    k_gemm<0><<<dim3(Mt, 2), 256>>>(x, lin1_w, lin1_b, nullptr, N, 128, 256,
                                    nullptr, nullptr, 0, 0.f);

    for (int l = 0; l < NL; l++) {
        k_gather<<<(N * 32 + 255) / 256, 256>>>(N);
        k_mma<<<Mt, 256, SMTOT>>>(l, N);
        if (l < NL - 1)
            k_norm<<<1184, 256>>>(gamma + l * DH, betab + l * DH, total4, Mt, invcnt);
    }

    // out = relu(norm7(g_ha) @ lin2_w + b)
    k_gemm<2><<<dim3(Mt, 1), 256>>>(nullptr, lin2_w, lin2_b, out, N, 256, 128,
                                    gamma + 7 * DH, betab + 7 * DH, Mt, invcnt);
}

// round 12
// speedup vs baseline: 1.8868x; 1.0474x over previous
#include <cuda_runtime.h>
#include <cuda_fp16.h>
#include <math.h>
#include <stdint.h>

#define NN 50000
#define EE 800000
#define DH 256
#define NL 8
#define NTILES ((NN + 127) / 128)        // 391
#define NPAD (NTILES * 128)              // 50048
#define NT2 ((NN + 255) / 256)           // 196
#define NPAD2 (NT2 * 256)                // 50176

// ---------------- scratch ----------------
__device__ float g_ha[NN * DH];                                  // fp32 h_out (per-layer)
__device__ __align__(16) __half g_hn[(size_t)NPAD2 * DH];        // fp16 relu(norm(h)) / x0 (padded for lin2 tiles)
__device__ __align__(16) __half g_a[(size_t)NPAD * 512];         // fp16 A [node][k] k<256 agg, k>=256 x0
__device__ __align__(16) __half g_bh[(size_t)NL * 512 * 256];    // B' hi
__device__ __align__(16) __half g_bl[(size_t)NL * 512 * 256];    // B' lo
__device__ __align__(16) __half g_x16[(size_t)NPAD * 128];       // fp16 x
__device__ __align__(16) __half g_w1h[128 * 256], g_w1l[128 * 256];
__device__ __align__(16) __half g_w2h[256 * 128], g_w2l[256 * 128];
__device__ float g_dis[NN];
__device__ int   g_counts[NN];
__device__ int   g_cursor[NN];
__device__ int   g_rowptr[NN + 1];
__device__ int   g_csr[EE];
__device__ float g_part[NTILES + 8];
__device__ float g_part2[NTILES + 8];

// ---------------- helpers ----------------
__device__ __forceinline__ uint32_t s2u(const void* p) {
    uint32_t a;
    asm("{ .reg .u64 t; cvta.to.shared.u64 t, %1; cvt.u32.u64 %0, t; }" : "=r"(a) : "l"(p));
    return a;
}
__device__ __forceinline__ void cp16(uint32_t dst, const void* src) {
    asm volatile("cp.async.cg.shared.global [%0], [%1], 16;" :: "r"(dst), "l"(src) : "memory");
}
#define CP_COMMIT() asm volatile("cp.async.commit_group;" ::: "memory")
#define CP_WAIT(n)  asm volatile("cp.async.wait_group %0;" :: "n"(n) : "memory")

#define LDSM4(r0,r1,r2,r3,a) \
    asm volatile("ldmatrix.sync.aligned.m8n8.x4.shared.b16 {%0,%1,%2,%3}, [%4];" \
                 : "=r"(r0),"=r"(r1),"=r"(r2),"=r"(r3) : "r"(a))
#define LDSM4T(r0,r1,r2,r3,a) \
    asm volatile("ldmatrix.sync.aligned.m8n8.x4.trans.shared.b16 {%0,%1,%2,%3}, [%4];" \
                 : "=r"(r0),"=r"(r1),"=r"(r2),"=r"(r3) : "r"(a))
#define MMA_F16(c,a,b0,b1) \
    asm volatile("mma.sync.aligned.m16n8k16.row.col.f32.f16.f16.f32 " \
                 "{%0,%1,%2,%3}, {%4,%5,%6,%7}, {%8,%9}, {%0,%1,%2,%3};" \
                 : "+f"((c)[0]),"+f"((c)[1]),"+f"((c)[2]),"+f"((c)[3]) \
                 : "r"((a)[0]),"r"((a)[1]),"r"((a)[2]),"r"((a)[3]),"r"(b0),"r"(b1))

__device__ __forceinline__ void split_h(float v, __half& h, __half& l) {
    h = __float2half_rn(v);
    l = __float2half_rn(v - __half2float(h));
}

// ---------------- graph preprocessing ----------------
__global__ void k_init(int n) {
    int i = blockIdx.x * blockDim.x + threadIdx.x;
    if (i < n) { g_counts[i] = 0; g_cursor[i] = 0; }
}
__global__ void k_count(const int* __restrict__ col, int E) {
    int e = blockIdx.x * blockDim.x + threadIdx.x;
    if (e < E) atomicAdd(&g_counts[col[e]], 1);
}
__global__ void k_scan(int n, int E) {
    __shared__ int sh[1024];
    int tid = threadIdx.x;
    int C = (n + 1023) >> 10;
    int base = tid * C;
    int s = 0;
    for (int i = 0; i < C; i++) { int idx = base + i; if (idx < n) s += g_counts[idx]; }
    sh[tid] = s; __syncthreads();
    for (int off = 1; off < 1024; off <<= 1) {
        int v = (tid >= off) ? sh[tid - off] : 0;
        __syncthreads();
        sh[tid] += v;
        __syncthreads();
    }
    int run = (tid > 0) ? sh[tid - 1] : 0;
    for (int i = 0; i < C; i++) {
        int idx = base + i;
        if (idx < n) {
            g_rowptr[idx] = run;
            int c = g_counts[idx];
            run += c;
            g_dis[idx] = rsqrtf((float)(c + 1));
        }
    }
    if (tid == 0) g_rowptr[n] = E;
}
__global__ void k_scatter(const int* __restrict__ row, const int* __restrict__ col, int E) {
    int e = blockIdx.x * blockDim.x + threadIdx.x;
    if (e < E) {
        int c = col[e];
        int p = g_rowptr[c] + atomicAdd(&g_cursor[c], 1);
        g_csr[p] = row[e];
    }
}

// ---------------- weight / input prep ----------------
__global__ void k_prep_b(const float* __restrict__ w1, const float* __restrict__ w2) {
    int idx = blockIdx.x * blockDim.x + threadIdx.x;
    if (idx >= NL * 512 * 256) return;
    int n = idx & 255;
    int k = (idx >> 8) & 511;
    int l = idx >> 17;
    float beta = logf(1.0f / (float)(l + 1) + 1.0f);
    float v = (k < 256) ? w1[(l << 16) + (k << 8) + n]
                        : w2[(l << 16) + ((k - 256) << 8) + n];
    float val = 0.5f * beta * v;
    if (k == n || k == n + 256) val += 0.5f * (1.0f - beta);
    split_h(val, g_bh[idx], g_bl[idx]);
}
__global__ void k_prep_x(const float* __restrict__ x, int total) {
    int i = blockIdx.x * blockDim.x + threadIdx.x;
    if (i < total) g_x16[i] = __float2half_rn(x[i]);
}
__global__ void k_prep_w(const float* __restrict__ w1, const float* __restrict__ w2) {
    int i = blockIdx.x * blockDim.x + threadIdx.x;
    if (i < 128 * 256) {
        split_h(w1[i], g_w1h[i], g_w1l[i]);
    } else if (i < 128 * 256 + 256 * 128) {
        int j = i - 128 * 256;
        split_h(w2[j], g_w2h[j], g_w2l[j]);
    }
}

// ---------------- CSR gather (fp16 in) -> fp16 A rows (k 0..255) ----------------
__global__ __launch_bounds__(256) void k_gather(int n) {
    int w = (blockIdx.x * blockDim.x + threadIdx.x) >> 5;
    int lane = threadIdx.x & 31;
    if (w >= n) return;
    const uint4* __restrict__ hn = (const uint4*)g_hn;
    float dc = g_dis[w];
    float a[8];
    {
        uint4 v = hn[w * 32 + lane];
        const __half2* ph = (const __half2*)&v;
#pragma unroll
        for (int j = 0; j < 4; j++) {
            float2 f = __half22float2(ph[j]);
            a[2 * j] = dc * f.x; a[2 * j + 1] = dc * f.y;
        }
    }
    int beg = g_rowptr[w], end = g_rowptr[w + 1];
    int i = beg;
    for (; i + 3 < end; i += 4) {
        int s0 = g_csr[i], s1 = g_csr[i + 1], s2 = g_csr[i + 2], s3 = g_csr[i + 3];
        float w0 = g_dis[s0], w1 = g_dis[s1], w2 = g_dis[s2], w3 = g_dis[s3];
        uint4 p = hn[s0 * 32 + lane], q = hn[s1 * 32 + lane];
        uint4 r = hn[s2 * 32 + lane], t = hn[s3 * 32 + lane];
        const __half2* pp = (const __half2*)&p;
        const __half2* qq = (const __half2*)&q;
        const __half2* rr = (const __half2*)&r;
        const __half2* tt = (const __half2*)&t;
#pragma unroll
        for (int j = 0; j < 4; j++) {
            float2 fp = __half22float2(pp[j]);
            float2 fq = __half22float2(qq[j]);
            float2 fr = __half22float2(rr[j]);
            float2 ft = __half22float2(tt[j]);
            a[2 * j]     = fmaf(w0, fp.x, fmaf(w1, fq.x, fmaf(w2, fr.x, fmaf(w3, ft.x, a[2 * j]))));
            a[2 * j + 1] = fmaf(w0, fp.y, fmaf(w1, fq.y, fmaf(w2, fr.y, fmaf(w3, ft.y, a[2 * j + 1]))));
        }
    }
    for (; i < end; i++) {
        int s0 = g_csr[i];
        float w0 = g_dis[s0];
        uint4 p = hn[s0 * 32 + lane];
        const __half2* pp = (const __half2*)&p;
#pragma unroll
        for (int j = 0; j < 4; j++) {
            float2 fp = __half22float2(pp[j]);
            a[2 * j]     = fmaf(w0, fp.x, a[2 * j]);
            a[2 * j + 1] = fmaf(w0, fp.y, a[2 * j + 1]);
        }
    }
    size_t ro = (size_t)w * 512 + lane * 8;
    __half hh[8];
#pragma unroll
    for (int j = 0; j < 8; j++) hh[j] = __float2half_rn(a[j] * dc);
    *(uint4*)&g_a[ro] = *(uint4*)hh;
}

// ---------------- layer GEMM: fp16 2-pass, 128m x 256n, K=512 (8x64) ----------------
#define STAGE 81920u
#define SMTOT 163840
__global__ __launch_bounds__(256, 1) void k_mma(int layer, int nvalid) {
    extern __shared__ char smem[];
    uint32_t sb = s2u(smem);
    const int tid = threadIdx.x, lane = tid & 31, wid = tid >> 5;
    const int T = blockIdx.x;

    const __half* __restrict__ Ag = g_a + (size_t)T * 128 * 512;
    const __half* __restrict__ Bgh = g_bh + (size_t)layer * 512 * 256;
    const __half* __restrict__ Bgl = g_bl + (size_t)layer * 512 * 256;

    auto load_chunk = [&](int c, int st) {
        uint32_t s0 = sb + st * STAGE;
#pragma unroll
        for (int i = 0; i < 4; i++) {
            int e = tid + i * 256;
            int m = e >> 3, kc = e & 7;
            uint32_t da = (uint32_t)(m * 128 + ((kc ^ (m & 7)) << 4));
            cp16(s0 + da, Ag + (size_t)m * 512 + c * 64 + kc * 8);
        }
#pragma unroll
        for (int i = 0; i < 8; i++) {
            int e = tid + i * 256;
            int k = e >> 5, ncol = e & 31;
            int nhalf = ncol >> 4, nc = ncol & 15;
            uint32_t db = (uint32_t)(nhalf * 16384 + k * 256 + ((nc ^ (k & 7)) << 4));
            size_t src = (size_t)(c * 64 + k) * 256 + nhalf * 128 + nc * 8;
            cp16(s0 + 16384 + db, Bgh + src);
            cp16(s0 + 49152 + db, Bgl + src);
        }
        CP_COMMIT();
    };

    float acc[4][8][4];
#pragma unroll
    for (int i = 0; i < 4; i++)
#pragma unroll
        for (int j = 0; j < 8; j++)
#pragma unroll
            for (int q = 0; q < 4; q++) acc[i][j][q] = 0.f;

    const int wm = (wid & 1) * 64;
    const int wng = (wid >> 1) * 64;
    const uint32_t nhb = (uint32_t)((wng >> 7) * 16384);
    const int ncb = (wng & 127) >> 3;

    auto compute = [&](uint32_t s0) {
        uint32_t sa = s0, sbh = s0 + 16384, sbl = s0 + 49152;
#pragma unroll
        for (int kq = 0; kq < 4; kq++) {
            uint32_t ar[4][4], bh[4][4], bl[4][4];
#pragma unroll
            for (int mi = 0; mi < 4; mi++) {
                int m = wm + mi * 16 + (lane & 15);
                int kcc = kq * 2 + (lane >> 4);
                uint32_t ad = (uint32_t)(m * 128 + ((kcc ^ (m & 7)) << 4));
                LDSM4(ar[mi][0], ar[mi][1], ar[mi][2], ar[mi][3], sa + ad);
            }
#pragma unroll
            for (int nj = 0; nj < 4; nj++) {
                int kr = kq * 16 + (lane & 15);
                int nc = ncb + nj * 2 + (lane >> 4);
                uint32_t bd = nhb + (uint32_t)(kr * 256 + ((nc ^ (kr & 7)) << 4));
                LDSM4T(bh[nj][0], bh[nj][1], bh[nj][2], bh[nj][3], sbh + bd);
                LDSM4T(bl[nj][0], bl[nj][1], bl[nj][2], bl[nj][3], sbl + bd);
            }
#pragma unroll
            for (int mi = 0; mi < 4; mi++)
#pragma unroll
                for (int nt = 0; nt < 8; nt++) {
                    int nj = nt >> 1, pq = (nt & 1) * 2;
                    MMA_F16(acc[mi][nt], ar[mi], bh[nj][pq], bh[nj][pq + 1]);
                    MMA_F16(acc[mi][nt], ar[mi], bl[nj][pq], bl[nj][pq + 1]);
                }
        }
    };

    load_chunk(0, 0);
    for (int ch = 0; ch < 8; ch++) {
        if (ch < 7) { load_chunk(ch + 1, (ch + 1) & 1); CP_WAIT(1); }
        else        { CP_WAIT(0); }
        __syncthreads();
        compute(sb + (ch & 1) * STAGE);
        __syncthreads();
    }

    float s = 0.f, ss = 0.f;
    int rbase = T * 128 + wm + (lane >> 2);
    int cbase = wng + (lane & 3) * 2;
#pragma unroll
    for (int mi = 0; mi < 4; mi++) {
        int r0 = rbase + mi * 16;
        int r1 = r0 + 8;
        bool v0 = r0 < nvalid, v1 = r1 < nvalid;
#pragma unroll
        for (int nt = 0; nt < 8; nt++) {
            int col = cbase + nt * 8;
            if (v0) {
                float2 p = make_float2(acc[mi][nt][0], acc[mi][nt][1]);
                *(float2*)&g_ha[(size_t)r0 * DH + col] = p;
                s += p.x + p.y; ss += p.x * p.x + p.y * p.y;
            }
            if (v1) {
                float2 p = make_float2(acc[mi][nt][2], acc[mi][nt][3]);
                *(float2*)&g_ha[(size_t)r1 * DH + col] = p;
                s += p.x + p.y; ss += p.x * p.x + p.y * p.y;
            }
        }
    }
    __syncthreads();
    float* red = (float*)smem;
    red[tid] = s; red[256 + tid] = ss;
    __syncthreads();
    for (int o = 128; o > 0; o >>= 1) {
        if (tid < o) { red[tid] += red[tid + o]; red[256 + tid] += red[256 + tid + o]; }
        __syncthreads();
    }
    if (tid == 0) { g_part[T] = red[0]; g_part2[T] = red[256]; }
}

// ---------------- lin1: fp16 2-pass, 128m x 256n, K=128 (2x64) -> g_hn + g_a[.,256:] ----------------
__global__ __launch_bounds__(256, 1) void k_lin1(const float* __restrict__ bias, int nvalid) {
    extern __shared__ char smem[];
    uint32_t sb = s2u(smem);
    const int tid = threadIdx.x, lane = tid & 31, wid = tid >> 5;
    const int T = blockIdx.x;

    auto load_chunk = [&](int c, int st) {
        uint32_t s0 = sb + st * STAGE;
#pragma unroll
        for (int i = 0; i < 4; i++) {
            int e = tid + i * 256;
            int m = e >> 3, kc = e & 7;
            uint32_t da = (uint32_t)(m * 128 + ((kc ^ (m & 7)) << 4));
            cp16(s0 + da, g_x16 + (size_t)(T * 128 + m) * 128 + c * 64 + kc * 8);
        }
#pragma unroll
        for (int i = 0; i < 8; i++) {
            int e = tid + i * 256;
            int k = e >> 5, ncol = e & 31;
            int nhalf = ncol >> 4, nc = ncol & 15;
            uint32_t db = (uint32_t)(nhalf * 16384 + k * 256 + ((nc ^ (k & 7)) << 4));
            size_t src = (size_t)(c * 64 + k) * 256 + nhalf * 128 + nc * 8;
            cp16(s0 + 16384 + db, g_w1h + src);
            cp16(s0 + 49152 + db, g_w1l + src);
        }
        CP_COMMIT();
    };

    float acc[4][8][4];
#pragma unroll
    for (int i = 0; i < 4; i++)
#pragma unroll
        for (int j = 0; j < 8; j++)
#pragma unroll
            for (int q = 0; q < 4; q++) acc[i][j][q] = 0.f;

    const int wm = (wid & 1) * 64;
    const int wng = (wid >> 1) * 64;
    const uint32_t nhb = (uint32_t)((wng >> 7) * 16384);
    const int ncb = (wng & 127) >> 3;

    auto compute = [&](uint32_t s0) {
        uint32_t sa = s0, sbh = s0 + 16384, sbl = s0 + 49152;
#pragma unroll
        for (int kq = 0; kq < 4; kq++) {
            uint32_t ar[4][4], bh[4][4], bl[4][4];
#pragma unroll
            for (int mi = 0; mi < 4; mi++) {
                int m = wm + mi * 16 + (lane & 15);
                int kcc = kq * 2 + (lane >> 4);
                uint32_t ad = (uint32_t)(m * 128 + ((kcc ^ (m & 7)) << 4));
                LDSM4(ar[mi][0], ar[mi][1], ar[mi][2], ar[mi][3], sa + ad);
            }
#pragma unroll
            for (int nj = 0; nj < 4; nj++) {
                int kr = kq * 16 + (lane & 15);
                int nc = ncb + nj * 2 + (lane >> 4);
                uint32_t bd = nhb + (uint32_t)(kr * 256 + ((nc ^ (kr & 7)) << 4));
                LDSM4T(bh[nj][0], bh[nj][1], bh[nj][2], bh[nj][3], sbh + bd);
                LDSM4T(bl[nj][0], bl[nj][1], bl[nj][2], bl[nj][3], sbl + bd);
            }
#pragma unroll
            for (int mi = 0; mi < 4; mi++)
#pragma unroll
                for (int nt = 0; nt < 8; nt++) {
                    int nj = nt >> 1, pq = (nt & 1) * 2;
                    MMA_F16(acc[mi][nt], ar[mi], bh[nj][pq], bh[nj][pq + 1]);
                    MMA_F16(acc[mi][nt], ar[mi], bl[nj][pq], bl[nj][pq + 1]);
                }
        }
    };

    load_chunk(0, 0);
    load_chunk(1, 1);
    CP_WAIT(1);
    __syncthreads();
    compute(sb);
    __syncthreads();
    CP_WAIT(0);
    __syncthreads();
    compute(sb + STAGE);

    int rbase = T * 128 + wm + (lane >> 2);
    int cbase = wng + (lane & 3) * 2;
#pragma unroll
    for (int mi = 0; mi < 4; mi++) {
        int r0 = rbase + mi * 16;
        int r1 = r0 + 8;
#pragma unroll
        for (int nt = 0; nt < 8; nt++) {
            int col = cbase + nt * 8;
            float2 bb = *(const float2*)&bias[col];
            float v0 = fmaxf(acc[mi][nt][0] + bb.x, 0.f);
            float v1 = fmaxf(acc[mi][nt][1] + bb.y, 0.f);
            __half2 h01 = __floats2half2_rn(v0, v1);
            *(__half2*)&g_a[(size_t)r0 * 512 + 256 + col] = h01;
            if (r0 < nvalid) *(__half2*)&g_hn[(size_t)r0 * DH + col] = h01;
            float v2 = fmaxf(acc[mi][nt][2] + bb.x, 0.f);
            float v3 = fmaxf(acc[mi][nt][3] + bb.y, 0.f);
            __half2 h23 = __floats2half2_rn(v2, v3);
            *(__half2*)&g_a[(size_t)r1 * 512 + 256 + col] = h23;
            if (r1 < nvalid) *(__half2*)&g_hn[(size_t)r1 * DH + col] = h23;
        }
    }
}

// ---------------- lin2: fp16 2-pass, 256m x 128n, K=256 (4x64): out = relu(g_hn @ W2 + b) ----------------
#define L2STAGE 65536u
#define L2SMTOT 131072
__global__ __launch_bounds__(256, 1) void k_lin2(const float* __restrict__ bias,
                                                 float* __restrict__ out, int nvalid) {
    extern __shared__ char smem[];
    uint32_t sb = s2u(smem);
    const int tid = threadIdx.x, lane = tid & 31, wid = tid >> 5;
    const int T = blockIdx.x;

    auto load_chunk = [&](int c, int st) {
        uint32_t s0 = sb + st * L2STAGE;
        // A: 256 rows x 64k = 2048 units (32KB)
#pragma unroll
        for (int i = 0; i < 8; i++) {
            int e = tid + i * 256;
            int m = e >> 3, kc = e & 7;
            uint32_t da = (uint32_t)(m * 128 + ((kc ^ (m & 7)) << 4));
            cp16(s0 + da, g_hn + (size_t)(T * 256 + m) * DH + c * 64 + kc * 8);
        }
        // B: 64k x 128n = 1024 units per hi/lo (16KB each)
#pragma unroll
        for (int i = 0; i < 4; i++) {
            int e = tid + i * 256;
            int k = e >> 4, nc = e & 15;
            uint32_t db = (uint32_t)(k * 256 + ((nc ^ (k & 7)) << 4));
            size_t src = (size_t)(c * 64 + k) * 128 + nc * 8;
            cp16(s0 + 32768 + db, g_w2h + src);
            cp16(s0 + 49152 + db, g_w2l + src);
        }
        CP_COMMIT();
    };

    float acc[4][8][4];
#pragma unroll
    for (int i = 0; i < 4; i++)
#pragma unroll
        for (int j = 0; j < 8; j++)
#pragma unroll
            for (int q = 0; q < 4; q++) acc[i][j][q] = 0.f;

    const int wm = (wid & 3) * 64;       // 4 m-warps over 256 rows
    const int wn = (wid >> 2) * 64;      // 2 n-warps over 128 cols
    const int ncb = wn >> 3;

    auto compute = [&](uint32_t s0) {
        uint32_t sa = s0, sbh = s0 + 32768, sbl = s0 + 49152;
#pragma unroll
        for (int kq = 0; kq < 4; kq++) {
            uint32_t ar[4][4], bh[4][4], bl[4][4];
#pragma unroll
            for (int mi = 0; mi < 4; mi++) {
                int m = wm + mi * 16 + (lane & 15);
                int kcc = kq * 2 + (lane >> 4);
                uint32_t ad = (uint32_t)(m * 128 + ((kcc ^ (m & 7)) << 4));
                LDSM4(ar[mi][0], ar[mi][1], ar[mi][2], ar[mi][3], sa + ad);
            }
#pragma unroll
            for (int nj = 0; nj < 4; nj++) {
                int kr = kq * 16 + (lane & 15);
                int nc = ncb + nj * 2 + (lane >> 4);
                uint32_t bd = (uint32_t)(kr * 256 + ((nc ^ (kr & 7)) << 4));
                LDSM4T(bh[nj][0], bh[nj][1], bh[nj][2], bh[nj][3], sbh + bd);
                LDSM4T(bl[nj][0], bl[nj][1], bl[nj][2], bl[nj][3], sbl + bd);
            }
#pragma unroll
            for (int mi = 0; mi < 4; mi++)
#pragma unroll
                for (int nt = 0; nt < 8; nt++) {
                    int nj = nt >> 1, pq = (nt & 1) * 2;
                    MMA_F16(acc[mi][nt], ar[mi], bh[nj][pq], bh[nj][pq + 1]);
                    MMA_F16(acc[mi][nt], ar[mi], bl[nj][pq], bl[nj][pq + 1]);
                }
        }
    };

    load_chunk(0, 0);
    for (int ch = 0; ch < 4; ch++) {
        if (ch < 3) { load_chunk(ch + 1, (ch + 1) & 1); CP_WAIT(1); }
        else        { CP_WAIT(0); }
        __syncthreads();
        compute(sb + (ch & 1) * L2STAGE);
        __syncthreads();
    }

    int rbase = T * 256 + wm + (lane >> 2);
    int cbase = wn + (lane & 3) * 2;
#pragma unroll
    for (int mi = 0; mi < 4; mi++) {
        int r0 = rbase + mi * 16;
        int r1 = r0 + 8;
        bool v0 = r0 < nvalid, v1 = r1 < nvalid;
#pragma unroll
        for (int nt = 0; nt < 8; nt++) {
            int col = cbase + nt * 8;
            float2 bb = *(const float2*)&bias[col];
            if (v0) {
                float2 p = make_float2(fmaxf(acc[mi][nt][0] + bb.x, 0.f),
                                       fmaxf(acc[mi][nt][1] + bb.y, 0.f));
                *(float2*)&out[(size_t)r0 * 128 + col] = p;
            }
            if (v1) {
                float2 p = make_float2(fmaxf(acc[mi][nt][2] + bb.x, 0.f),
                                       fmaxf(acc[mi][nt][3] + bb.y, 0.f));
                *(float2*)&out[(size_t)r1 * 128 + col] = p;
            }
        }
    }
}

// ---------------- layernorm: finalize + normalize+relu, fp32 g_ha -> fp16 g_hn ----------------
__global__ __launch_bounds__(256) void k_norm(const float* __restrict__ gamma,
                                              const float* __restrict__ beta,
                                              int total4, int nparts, float invcnt) {
    __shared__ float sred[512];
    __shared__ float s_scale[256], s_shift[256];
    const int tid = threadIdx.x;

    float s = 0.f, ss = 0.f;
    for (int i = tid; i < nparts; i += 256) { s += g_part[i]; ss += g_part2[i]; }
    sred[tid] = s; sred[256 + tid] = ss;
    __syncthreads();
    for (int o = 128; o > 0; o >>= 1) {
        if (tid < o) { sred[tid] += sred[tid + o]; sred[256 + tid] += sred[256 + tid + o]; }
        __syncthreads();
    }
    float mu = sred[0] * invcnt;
    float var = fmaxf(sred[256] * invcnt - mu * mu, 0.f);
    float inv = 1.0f / (sqrtf(var) + 1e-5f);
    float gch = gamma[tid] * inv;
    s_scale[tid] = gch;
    s_shift[tid] = beta[tid] - mu * gch;
    __syncthreads();

    int stride = gridDim.x * 256;
    for (int i = blockIdx.x * 256 + tid; i < total4; i += stride) {
        float4 v = ((const float4*)g_ha)[i];
        int f = (i * 4) & 255;
        float4 g = *(float4*)&s_scale[f];
        float4 b = *(float4*)&s_shift[f];
        v.x = fmaxf(fmaf(v.x, g.x, b.x), 0.f);
        v.y = fmaxf(fmaf(v.y, g.y, b.y), 0.f);
        v.z = fmaxf(fmaf(v.z, g.z, b.z), 0.f);
        v.w = fmaxf(fmaf(v.w, g.w, b.w), 0.f);
        __half2* dst = (__half2*)&g_hn[(size_t)i * 4];
        dst[0] = __floats2half2_rn(v.x, v.y);
        dst[1] = __floats2half2_rn(v.z, v.w);
    }
}

// ---------------- launch ----------------
extern "C" void kernel_launch(void* const* d_in, const int* in_sizes, int n_in,
                              void* d_out, int out_size) {
    const float* x      = (const float*)d_in[0];
    const int*   ei     = (const int*)d_in[1];
    const float* lin1_w = (const float*)d_in[2];
    const float* lin1_b = (const float*)d_in[3];
    const float* w1     = (const float*)d_in[4];
    const float* w2     = (const float*)d_in[5];
    const float* gamma  = (const float*)d_in[6];
    const float* betab  = (const float*)d_in[7];
    const float* lin2_w = (const float*)d_in[8];
    const float* lin2_b = (const float*)d_in[9];
    float* out = (float*)d_out;

    int N = in_sizes[0] / 128;
    int E = in_sizes[1] / 2;
    const int* row = ei;
    const int* col = ei + E;

    int Mt = (N + 127) / 128;
    int Mt2 = (N + 255) / 256;
    int total4 = N * (DH / 4);
    float invcnt = 1.0f / ((float)N * (float)DH);

    static int smem_set = 0;
    if (!smem_set) {
        cudaFuncSetAttribute(k_mma, cudaFuncAttributeMaxDynamicSharedMemorySize, SMTOT);
        cudaFuncSetAttribute(k_lin1, cudaFuncAttributeMaxDynamicSharedMemorySize, SMTOT);
        cudaFuncSetAttribute(k_lin2, cudaFuncAttributeMaxDynamicSharedMemorySize, L2SMTOT);
        smem_set = 1;
    }

    k_init<<<(N + 255) / 256, 256>>>(N);
    k_count<<<(E + 255) / 256, 256>>>(col, E);
    k_scan<<<1, 1024>>>(N, E);
    k_scatter<<<(E + 255) / 256, 256>>>(row, col, E);
    k_prep_b<<<(NL * 512 * 256 + 255) / 256, 256>>>(w1, w2);
    k_prep_x<<<(N * 128 + 255) / 256, 256>>>(x, N * 128);
    k_prep_w<<<(2 * 128 * 256 + 255) / 256, 256>>>(lin1_w, lin2_w);

    // x0 = relu(x @ lin1_w + b) -> g_hn + g_a upper-k (tensor path)
    k_lin1<<<Mt, 256, SMTOT>>>(lin1_b, N);

    for (int l = 0; l < NL; l++) {
        k_gather<<<(N * 32 + 255) / 256, 256>>>(N);
        k_mma<<<Mt, 256, SMTOT>>>(l, N);
        k_norm<<<1184, 256>>>(gamma + l * DH, betab + l * DH, total4, Mt, invcnt);
    }

    // out = relu(norm7(h) @ lin2_w + b) (tensor path, reads g_hn)
    k_lin2<<<Mt2, 256, L2SMTOT>>>(lin2_b, out, N);
}